// round 5
// baseline (speedup 1.0000x reference)
#include <cuda_runtime.h>
#include <cuda_bf16.h>

#define EMB 64
#define BN_EPS 1e-5f
#define MAX_L 50000
#define MAX_R 100000
#define MAX_E 1100000

// ---------------- scratch (static device globals; no allocation) -------------
__device__ float g_left_proj[MAX_L * EMB];
__device__ float g_right_proj[MAX_R * EMB];
__device__ float g_S[MAX_R * EMB];       // per-right-node sum of relu(bn1(joint))
__device__ float g_conv[MAX_R * EMB];
__device__ int   g_cnt[MAX_R];           // degree of each right node
__device__ int   g_off[MAX_R];           // segment start
__device__ int   g_cur[MAX_R];           // binning cursor
__device__ int   g_total;
__device__ int2  g_sorted[MAX_E];        // {left_idx, f_bits} grouped by right node
__device__ int   g_srtR[MAX_E];          // right index per sorted slot
__device__ float g_sum1[EMB], g_sumsq1[EMB], g_scale1[EMB], g_shift1[EMB];
__device__ float g_sum2[EMB], g_sumsq2[EMB], g_scale2[EMB], g_shift2[EMB];

// ---------------- zero scratch ----------------------------------------------
__global__ void zero_kernel(int nR, int nS) {
    int i = blockIdx.x * blockDim.x + threadIdx.x;
    int stride = gridDim.x * blockDim.x;
    for (int k = i; k < nR; k += stride) g_cnt[k] = 0;
    for (int k = i; k < nS; k += stride) g_S[k] = 0.f;
    if (i < EMB) { g_sum1[i] = 0.f; g_sumsq1[i] = 0.f; g_sum2[i] = 0.f; g_sumsq2[i] = 0.f; }
    if (i == 0) g_total = 0;
}

// ---------------- count: histogram of right indices --------------------------
__global__ __launch_bounds__(256) void count_kernel(const int* __restrict__ idxR, int nE) {
    int i = blockIdx.x * blockDim.x + threadIdx.x;
    int stride = gridDim.x * blockDim.x;
    for (int e = i; e < nE; e += stride) atomicAdd(&g_cnt[idxR[e]], 1);
}

// ---------------- assign: contiguous segment offsets (order-free) ------------
__global__ __launch_bounds__(256) void assign_kernel(int nR) {
    int gtid = blockIdx.x * blockDim.x + threadIdx.x;
    int lane = threadIdx.x & 31;
    int stride = gridDim.x * blockDim.x;
    int niter = (nR + stride - 1) / stride;
    for (int it = 0; it < niter; it++) {
        int i = it * stride + gtid;
        int c = (i < nR) ? g_cnt[i] : 0;
        int s = c;
        #pragma unroll
        for (int d = 1; d < 32; d <<= 1) {
            int t = __shfl_up_sync(0xffffffffu, s, d);
            if (lane >= d) s += t;
        }
        int warpTotal = __shfl_sync(0xffffffffu, s, 31);
        int base = 0;
        if (lane == 31) base = atomicAdd(&g_total, warpTotal);
        base = __shfl_sync(0xffffffffu, base, 31);
        int off = base + s - c;
        if (i < nR) { g_off[i] = off; g_cur[i] = off; }
    }
}

// ---------------- bin: place {li, f} and r into per-node segments ------------
__global__ __launch_bounds__(256) void bin_kernel(
    const int* __restrict__ idxL, const int* __restrict__ idxR,
    const float* __restrict__ ef, int nE)
{
    int i = blockIdx.x * blockDim.x + threadIdx.x;
    int stride = gridDim.x * blockDim.x;
    for (int e = i; e < nE; e += stride) {
        int r = idxR[e];
        int li = idxL[e];
        float f = ef[e];
        int pos = atomicAdd(&g_cur[r], 1);
        g_sorted[pos] = make_int2(li, __float_as_int(f));
        g_srtR[pos] = r;
    }
}

// ---------------- fused projections: left and right in one launch ------------
__global__ __launch_bounds__(128) void proj_kernel(
    const float* __restrict__ XL, const float* __restrict__ WL, const float* __restrict__ bL,
    const float* __restrict__ XR, const float* __restrict__ WR,
    int nL, int nR, int nbL)
{
    bool isL = (int)blockIdx.x < nbL;
    const float* X = isL ? XL : XR;
    const float* W = isL ? WL : WR;
    float* Y = isL ? g_left_proj : g_right_proj;
    int n = isL ? nL : nR;
    int bid = isL ? blockIdx.x : blockIdx.x - nbL;

    __shared__ float WT[EMB * EMB];
    __shared__ float bsh[EMB];
    for (int i = threadIdx.x; i < EMB * EMB; i += blockDim.x) {
        int j = i >> 6, k = i & 63;
        WT[k * EMB + j] = W[i];
    }
    if (threadIdx.x < EMB) bsh[threadIdx.x] = isL ? bL[threadIdx.x] : 0.f;
    __syncthreads();

    int row = bid * blockDim.x + threadIdx.x;
    if (row >= n) return;
    float acc[EMB];
    #pragma unroll
    for (int j = 0; j < EMB; j++) acc[j] = bsh[j];
    const float4* Xr = (const float4*)(X + (size_t)row * EMB);
    #pragma unroll 2
    for (int k4 = 0; k4 < EMB / 4; k4++) {
        float4 xv = Xr[k4];
        const float* wp = &WT[(k4 * 4) * EMB];
        #pragma unroll
        for (int j = 0; j < EMB; j++) acc[j] = fmaf(wp[j], xv.x, acc[j]);
        #pragma unroll
        for (int j = 0; j < EMB; j++) acc[j] = fmaf(wp[EMB + j], xv.y, acc[j]);
        #pragma unroll
        for (int j = 0; j < EMB; j++) acc[j] = fmaf(wp[2 * EMB + j], xv.z, acc[j]);
        #pragma unroll
        for (int j = 0; j < EMB; j++) acc[j] = fmaf(wp[3 * EMB + j], xv.w, acc[j]);
    }
    float4* Yr = (float4*)(Y + (size_t)row * EMB);
    #pragma unroll
    for (int q = 0; q < EMB / 4; q++)
        Yr[q] = make_float4(acc[4 * q], acc[4 * q + 1], acc[4 * q + 2], acc[4 * q + 3]);
}

// ---------------- BN1 stats: chunked over original edges (order-free) --------
__global__ __launch_bounds__(256) void stats_kernel(
    const int* __restrict__ idxL, const int* __restrict__ idxR,
    const float* __restrict__ ef, const float* __restrict__ Wedge, int nE)
{
    int lane = threadIdx.x & 31;
    int hl = lane & 15;
    unsigned hmask = (lane & 16) ? 0xFFFF0000u : 0x0000FFFFu;
    int grp = (blockIdx.x * blockDim.x + threadIdx.x) >> 4;
    int ngrp = (gridDim.x * blockDim.x) >> 4;
    float4 we = ((const float4*)Wedge)[hl];
    float4 s = make_float4(0.f, 0.f, 0.f, 0.f);
    float4 sq = make_float4(0.f, 0.f, 0.f, 0.f);
    const float4* LP = (const float4*)g_left_proj;
    const float4* RP = (const float4*)g_right_proj;

    int nfull = nE >> 4;
    for (int ch = grp; ch < nfull; ch += ngrp) {
        int e = (ch << 4) + hl;
        int li = idxL[e], ri = idxR[e];
        float f = ef[e];
        #pragma unroll
        for (int j = 0; j < 16; j++) {
            int lj   = __shfl_sync(hmask, li, j, 16);
            int rj   = __shfl_sync(hmask, ri, j, 16);
            float fj = __shfl_sync(hmask, f, j, 16);
            float4 lp = LP[(size_t)lj * 16 + hl];
            float4 rp = RP[(size_t)rj * 16 + hl];
            float x;
            x = fmaf(fj, we.x, lp.x + rp.x); s.x += x; sq.x = fmaf(x, x, sq.x);
            x = fmaf(fj, we.y, lp.y + rp.y); s.y += x; sq.y = fmaf(x, x, sq.y);
            x = fmaf(fj, we.z, lp.z + rp.z); s.z += x; sq.z = fmaf(x, x, sq.z);
            x = fmaf(fj, we.w, lp.w + rp.w); s.w += x; sq.w = fmaf(x, x, sq.w);
        }
    }
    if (grp == 0) {
        for (int e = nfull << 4; e < nE; e++) {
            int lj = idxL[e], rj = idxR[e];
            float fj = ef[e];
            float4 lp = LP[(size_t)lj * 16 + hl];
            float4 rp = RP[(size_t)rj * 16 + hl];
            float x;
            x = fmaf(fj, we.x, lp.x + rp.x); s.x += x; sq.x = fmaf(x, x, sq.x);
            x = fmaf(fj, we.y, lp.y + rp.y); s.y += x; sq.y = fmaf(x, x, sq.y);
            x = fmaf(fj, we.z, lp.z + rp.z); s.z += x; sq.z = fmaf(x, x, sq.z);
            x = fmaf(fj, we.w, lp.w + rp.w); s.w += x; sq.w = fmaf(x, x, sq.w);
        }
    }
    // combine halves, then block/global reduce
    s.x += __shfl_xor_sync(0xffffffffu, s.x, 16);
    s.y += __shfl_xor_sync(0xffffffffu, s.y, 16);
    s.z += __shfl_xor_sync(0xffffffffu, s.z, 16);
    s.w += __shfl_xor_sync(0xffffffffu, s.w, 16);
    sq.x += __shfl_xor_sync(0xffffffffu, sq.x, 16);
    sq.y += __shfl_xor_sync(0xffffffffu, sq.y, 16);
    sq.z += __shfl_xor_sync(0xffffffffu, sq.z, 16);
    sq.w += __shfl_xor_sync(0xffffffffu, sq.w, 16);

    __shared__ float cs[EMB], cq[EMB];
    if (threadIdx.x < EMB) { cs[threadIdx.x] = 0.f; cq[threadIdx.x] = 0.f; }
    __syncthreads();
    if (lane < 16) {
        atomicAdd(&cs[4 * hl + 0], s.x);
        atomicAdd(&cs[4 * hl + 1], s.y);
        atomicAdd(&cs[4 * hl + 2], s.z);
        atomicAdd(&cs[4 * hl + 3], s.w);
        atomicAdd(&cq[4 * hl + 0], sq.x);
        atomicAdd(&cq[4 * hl + 1], sq.y);
        atomicAdd(&cq[4 * hl + 2], sq.z);
        atomicAdd(&cq[4 * hl + 3], sq.w);
    }
    __syncthreads();
    if (threadIdx.x < EMB) {
        atomicAdd(&g_sum1[threadIdx.x], cs[threadIdx.x]);
        atomicAdd(&g_sumsq1[threadIdx.x], cq[threadIdx.x]);
    }
}

// ---------------- BN finalize ------------------------------------------------
__global__ void bn_fin_kernel(const float* __restrict__ sum, const float* __restrict__ sumsq,
                              const float* __restrict__ gamma, const float* __restrict__ beta,
                              float* __restrict__ scale, float* __restrict__ shift, float invN)
{
    int c = threadIdx.x;
    if (c < EMB) {
        float m = sum[c] * invN;
        float v = sumsq[c] * invN - m * m;
        float sc = gamma[c] * rsqrtf(v + BN_EPS);
        scale[c] = sc;
        shift[c] = beta[c] - m * sc;
    }
}

// ---------------- seg: chunked over sorted edges, run-length accumulate ------
__global__ __launch_bounds__(256) void seg_kernel(const float* __restrict__ Wedge, int nE)
{
    int lane = threadIdx.x & 31;
    int hl = lane & 15;
    unsigned hmask = (lane & 16) ? 0xFFFF0000u : 0x0000FFFFu;
    int grp = (blockIdx.x * blockDim.x + threadIdx.x) >> 4;
    int ngrp = (gridDim.x * blockDim.x) >> 4;
    float4 we = ((const float4*)Wedge)[hl];
    float4 sc = ((const float4*)g_scale1)[hl];
    float4 sh = ((const float4*)g_shift1)[hl];
    const float4* LP = (const float4*)g_left_proj;
    const float4* RP = (const float4*)g_right_proj;
    float4* Sv = (float4*)g_S;

    int nfull = nE >> 4;
    for (int ch = grp; ch < nfull; ch += ngrp) {
        int e = (ch << 4) + hl;
        int2 a = g_sorted[e];
        int r = g_srtR[e];
        int li = a.x;
        float f = __int_as_float(a.y);
        float4 acc = make_float4(0.f, 0.f, 0.f, 0.f);
        float4 rpv = make_float4(0.f, 0.f, 0.f, 0.f);
        int rprev = -1;
        #pragma unroll
        for (int j = 0; j < 16; j++) {
            int rj   = __shfl_sync(hmask, r, j, 16);
            int lj   = __shfl_sync(hmask, li, j, 16);
            float fj = __shfl_sync(hmask, f, j, 16);
            if (rj != rprev) {                       // uniform within 16-lane group
                if (rprev >= 0) atomicAdd(&Sv[(size_t)rprev * 16 + hl], acc);
                rpv = RP[(size_t)rj * 16 + hl];
                acc = make_float4(0.f, 0.f, 0.f, 0.f);
                rprev = rj;
            }
            float4 lp = LP[(size_t)lj * 16 + hl];
            float x;
            x = fmaf(fj, we.x, lp.x + rpv.x); acc.x += fmaxf(fmaf(x, sc.x, sh.x), 0.f);
            x = fmaf(fj, we.y, lp.y + rpv.y); acc.y += fmaxf(fmaf(x, sc.y, sh.y), 0.f);
            x = fmaf(fj, we.z, lp.z + rpv.z); acc.z += fmaxf(fmaf(x, sc.z, sh.z), 0.f);
            x = fmaf(fj, we.w, lp.w + rpv.w); acc.w += fmaxf(fmaf(x, sc.w, sh.w), 0.f);
        }
        if (rprev >= 0) atomicAdd(&Sv[(size_t)rprev * 16 + hl], acc);
    }
    if (grp == 0) {
        for (int e = nfull << 4; e < nE; e++) {
            int2 a = g_sorted[e];
            int rj = g_srtR[e];
            float4 lp = LP[(size_t)a.x * 16 + hl];
            float4 rp = RP[(size_t)rj * 16 + hl];
            float fj = __int_as_float(a.y);
            float4 y;
            float x;
            x = fmaf(fj, we.x, lp.x + rp.x); y.x = fmaxf(fmaf(x, sc.x, sh.x), 0.f);
            x = fmaf(fj, we.y, lp.y + rp.y); y.y = fmaxf(fmaf(x, sc.y, sh.y), 0.f);
            x = fmaf(fj, we.z, lp.z + rp.z); y.z = fmaxf(fmaf(x, sc.z, sh.z), 0.f);
            x = fmaf(fj, we.w, lp.w + rp.w); y.w = fmaxf(fmaf(x, sc.w, sh.w), 0.f);
            atomicAdd(&Sv[(size_t)rj * 16 + hl], y);
        }
    }
}

// ---------------- conv = S @ Wf^T + cnt*b, fused BN2 column stats ------------
__global__ __launch_bounds__(128) void conv_stats_kernel(
    const float* __restrict__ X, const float* __restrict__ W,
    const float* __restrict__ bias, float* __restrict__ Y, int n)
{
    __shared__ float WT[EMB * EMB];
    __shared__ float bsh[EMB];
    __shared__ float cs[EMB], cq[EMB];
    for (int i = threadIdx.x; i < EMB * EMB; i += blockDim.x) {
        int j = i >> 6, k = i & 63;
        WT[k * EMB + j] = W[i];
    }
    if (threadIdx.x < EMB) {
        bsh[threadIdx.x] = bias[threadIdx.x];
        cs[threadIdx.x] = 0.f;
        cq[threadIdx.x] = 0.f;
    }
    __syncthreads();

    int row = blockIdx.x * blockDim.x + threadIdx.x;
    int lane = threadIdx.x & 31;
    bool valid = row < n;
    float acc[EMB];
    if (valid) {
        float bs = (float)g_cnt[row];
        #pragma unroll
        for (int j = 0; j < EMB; j++) acc[j] = bsh[j] * bs;
        const float4* Xr = (const float4*)(X + (size_t)row * EMB);
        #pragma unroll 2
        for (int k4 = 0; k4 < EMB / 4; k4++) {
            float4 xv = Xr[k4];
            const float* wp = &WT[(k4 * 4) * EMB];
            #pragma unroll
            for (int j = 0; j < EMB; j++) acc[j] = fmaf(wp[j], xv.x, acc[j]);
            #pragma unroll
            for (int j = 0; j < EMB; j++) acc[j] = fmaf(wp[EMB + j], xv.y, acc[j]);
            #pragma unroll
            for (int j = 0; j < EMB; j++) acc[j] = fmaf(wp[2 * EMB + j], xv.z, acc[j]);
            #pragma unroll
            for (int j = 0; j < EMB; j++) acc[j] = fmaf(wp[3 * EMB + j], xv.w, acc[j]);
        }
        float4* Yr = (float4*)(Y + (size_t)row * EMB);
        #pragma unroll
        for (int q = 0; q < EMB / 4; q++)
            Yr[q] = make_float4(acc[4 * q], acc[4 * q + 1], acc[4 * q + 2], acc[4 * q + 3]);
    } else {
        #pragma unroll
        for (int j = 0; j < EMB; j++) acc[j] = 0.f;
    }
    #pragma unroll
    for (int j = 0; j < EMB; j++) {
        float v = acc[j];
        float v2 = v * v;
        #pragma unroll
        for (int o = 16; o; o >>= 1) {
            v  += __shfl_xor_sync(0xffffffffu, v, o);
            v2 += __shfl_xor_sync(0xffffffffu, v2, o);
        }
        if (lane == 0) { atomicAdd(&cs[j], v); atomicAdd(&cq[j], v2); }
    }
    __syncthreads();
    if (threadIdx.x < EMB) {
        atomicAdd(&g_sum2[threadIdx.x], cs[threadIdx.x]);
        atomicAdd(&g_sumsq2[threadIdx.x], cq[threadIdx.x]);
    }
}

// ---------------- final: bn2 + concat + 2-layer MLP --------------------------
__global__ __launch_bounds__(128) void final_kernel(
    const float* __restrict__ right,
    const float* __restrict__ W1, const float* __restrict__ b1,
    const float* __restrict__ W2, const float* __restrict__ b2,
    float* __restrict__ out, int nR)
{
    __shared__ float Wsh[2 * EMB * EMB];
    __shared__ float sb[EMB], ssc[EMB], ssh[EMB];
    for (int i = threadIdx.x; i < 2 * EMB * EMB; i += blockDim.x) {
        int j = i >> 7, c = i & 127;       // W1 is [64,128]
        Wsh[c * EMB + j] = W1[i];
    }
    if (threadIdx.x < EMB) {
        sb[threadIdx.x] = b1[threadIdx.x];
        ssc[threadIdx.x] = g_scale2[threadIdx.x];
        ssh[threadIdx.x] = g_shift2[threadIdx.x];
    }
    __syncthreads();

    int row = blockIdx.x * blockDim.x + threadIdx.x;
    float h[EMB];
    if (row < nR) {
        #pragma unroll
        for (int j = 0; j < EMB; j++) h[j] = sb[j];
        const float4* cv = (const float4*)(g_conv + (size_t)row * EMB);
        #pragma unroll 2
        for (int k4 = 0; k4 < 16; k4++) {
            float4 v = cv[k4];
            int c = k4 * 4;
            float x0 = fmaf(v.x, ssc[c], ssh[c]);
            float x1 = fmaf(v.y, ssc[c + 1], ssh[c + 1]);
            float x2 = fmaf(v.z, ssc[c + 2], ssh[c + 2]);
            float x3 = fmaf(v.w, ssc[c + 3], ssh[c + 3]);
            const float* wp = &Wsh[c * EMB];
            #pragma unroll
            for (int j = 0; j < EMB; j++) h[j] = fmaf(wp[j], x0, h[j]);
            #pragma unroll
            for (int j = 0; j < EMB; j++) h[j] = fmaf(wp[EMB + j], x1, h[j]);
            #pragma unroll
            for (int j = 0; j < EMB; j++) h[j] = fmaf(wp[2 * EMB + j], x2, h[j]);
            #pragma unroll
            for (int j = 0; j < EMB; j++) h[j] = fmaf(wp[3 * EMB + j], x3, h[j]);
        }
        const float4* rf = (const float4*)(right + (size_t)row * EMB);
        #pragma unroll 2
        for (int k4 = 0; k4 < 16; k4++) {
            float4 v = rf[k4];
            int c = 64 + k4 * 4;
            const float* wp = &Wsh[c * EMB];
            #pragma unroll
            for (int j = 0; j < EMB; j++) h[j] = fmaf(wp[j], v.x, h[j]);
            #pragma unroll
            for (int j = 0; j < EMB; j++) h[j] = fmaf(wp[EMB + j], v.y, h[j]);
            #pragma unroll
            for (int j = 0; j < EMB; j++) h[j] = fmaf(wp[2 * EMB + j], v.z, h[j]);
            #pragma unroll
            for (int j = 0; j < EMB; j++) h[j] = fmaf(wp[3 * EMB + j], v.w, h[j]);
        }
        #pragma unroll
        for (int j = 0; j < EMB; j++) h[j] = fmaxf(h[j], 0.f);
    }
    __syncthreads();
    for (int i = threadIdx.x; i < EMB * EMB; i += blockDim.x) {
        int j = i >> 6, c = i & 63;
        Wsh[c * EMB + j] = W2[i];
    }
    if (threadIdx.x < EMB) sb[threadIdx.x] = b2[threadIdx.x];
    __syncthreads();
    if (row < nR) {
        float* orow = out + (size_t)row * EMB;
        #pragma unroll
        for (int jb = 0; jb < 4; jb++) {
            float acc[16];
            #pragma unroll
            for (int j = 0; j < 16; j++) acc[j] = sb[jb * 16 + j];
            #pragma unroll 4
            for (int c = 0; c < EMB; c++) {
                float hc = h[c];
                const float* wp = &Wsh[c * EMB + jb * 16];
                #pragma unroll
                for (int j = 0; j < 16; j++) acc[j] = fmaf(wp[j], hc, acc[j]);
            }
            float4* o4 = (float4*)(orow + jb * 16);
            #pragma unroll
            for (int q = 0; q < 4; q++)
                o4[q] = make_float4(fmaxf(acc[4 * q], 0.f), fmaxf(acc[4 * q + 1], 0.f),
                                    fmaxf(acc[4 * q + 2], 0.f), fmaxf(acc[4 * q + 3], 0.f));
        }
    }
}

// ---------------- launch -----------------------------------------------------
extern "C" void kernel_launch(void* const* d_in, const int* in_sizes, int n_in,
                              void* d_out, int out_size)
{
    const float* left  = (const float*)d_in[0];
    const int*   eidx  = (const int*)d_in[1];
    const float* ef    = (const float*)d_in[2];
    const float* right = (const float*)d_in[3];
    int off = (n_in >= 19) ? 1 : 0;
    const float* W_left    = (const float*)d_in[4 + off];
    const float* b_left    = (const float*)d_in[5 + off];
    const float* W_edge    = (const float*)d_in[6 + off];
    const float* W_right   = (const float*)d_in[7 + off];
    const float* bn1_gamma = (const float*)d_in[8 + off];
    const float* bn1_beta  = (const float*)d_in[9 + off];
    const float* W_final   = (const float*)d_in[10 + off];
    const float* b_final   = (const float*)d_in[11 + off];
    const float* bn2_gamma = (const float*)d_in[12 + off];
    const float* bn2_beta  = (const float*)d_in[13 + off];
    const float* W_out1    = (const float*)d_in[14 + off];
    const float* b_out1    = (const float*)d_in[15 + off];
    const float* W_out2    = (const float*)d_in[16 + off];
    const float* b_out2    = (const float*)d_in[17 + off];
    float* out = (float*)d_out;

    int nL = in_sizes[0] / EMB;
    int nE = in_sizes[2];
    int nR = in_sizes[3] / EMB;

    float* Sp; cudaGetSymbolAddress((void**)&Sp, g_S);
    float* cp; cudaGetSymbolAddress((void**)&cp, g_conv);
    float* s1; cudaGetSymbolAddress((void**)&s1, g_sum1);
    float* q1; cudaGetSymbolAddress((void**)&q1, g_sumsq1);
    float* sc1; cudaGetSymbolAddress((void**)&sc1, g_scale1);
    float* sh1; cudaGetSymbolAddress((void**)&sh1, g_shift1);
    float* s2; cudaGetSymbolAddress((void**)&s2, g_sum2);
    float* q2; cudaGetSymbolAddress((void**)&q2, g_sumsq2);
    float* sc2; cudaGetSymbolAddress((void**)&sc2, g_scale2);
    float* sh2; cudaGetSymbolAddress((void**)&sh2, g_shift2);

    int nbL = (nL + 127) / 128;
    int nbR = (nR + 127) / 128;

    // 0) zero counters/stats/S
    zero_kernel<<<1024, 256>>>(nR, nR * EMB);
    // 1) degree histogram
    count_kernel<<<1184, 256>>>(eidx + nE, nE);
    // 2) contiguous segment offsets
    assign_kernel<<<(nR + 255) / 256, 256>>>(nR);
    // 3) bin {left_idx, f, r} into segments
    bin_kernel<<<1184, 256>>>(eidx, eidx + nE, ef, nE);
    // 4) projections
    proj_kernel<<<nbL + nbR, 128>>>(left, W_left, b_left, right, W_right, nL, nR, nbL);
    // 5) BN1 stats (chunked, original order)           <- profiled launch (-s 5)
    stats_kernel<<<1184, 256>>>(eidx, eidx + nE, ef, W_edge, nE);
    bn_fin_kernel<<<1, EMB>>>(s1, q1, bn1_gamma, bn1_beta, sc1, sh1, 1.0f / (float)nE);
    // 6) segment sum over sorted edges, run-length accumulated
    seg_kernel<<<1184, 256>>>(W_edge, nE);
    // 7) conv = S @ W_final^T + cnt * b_final, fused BN2 stats
    conv_stats_kernel<<<nbR, 128>>>(Sp, W_final, b_final, cp, nR);
    bn_fin_kernel<<<1, EMB>>>(s2, q2, bn2_gamma, bn2_beta, sc2, sh2, 1.0f / (float)nR);
    // 8) final MLP
    final_kernel<<<nbR, 128>>>(right, W_out1, b_out1, W_out2, b_out2, out, nR);
}

// round 6
// speedup vs baseline: 1.0467x; 1.0467x over previous
#include <cuda_runtime.h>
#include <cuda_bf16.h>

#define EMB 64
#define BN_EPS 1e-5f
#define MAX_L 50000
#define MAX_R 100000
#define MAX_E 1100000

// ---------------- scratch (static device globals; no allocation) -------------
__device__ float g_left_proj[MAX_L * EMB];
__device__ float g_right_proj[MAX_R * EMB];
__device__ float g_S[MAX_R * EMB];       // per-right-node sum of relu(bn1(joint))
__device__ float g_conv[MAX_R * EMB];
__device__ int   g_cnt[MAX_R];           // degree of each right node
__device__ int   g_off[MAX_R];           // segment start
__device__ int   g_cur[MAX_R];           // binning cursor
__device__ int   g_total;
__device__ int2  g_sorted[MAX_E];        // {left_idx, f_bits} grouped by right node
__device__ int   g_srtR[MAX_E];          // right index per sorted slot
__device__ float g_sum1[EMB], g_sumsq1[EMB], g_scale1[EMB], g_shift1[EMB];
__device__ float g_sum2[EMB], g_sumsq2[EMB], g_scale2[EMB], g_shift2[EMB];

// ---------------- zero scratch ----------------------------------------------
__global__ void zero_kernel(int nR, int nS) {
    int i = blockIdx.x * blockDim.x + threadIdx.x;
    int stride = gridDim.x * blockDim.x;
    for (int k = i; k < nR; k += stride) g_cnt[k] = 0;
    for (int k = i; k < nS; k += stride) g_S[k] = 0.f;
    if (i < EMB) { g_sum1[i] = 0.f; g_sumsq1[i] = 0.f; g_sum2[i] = 0.f; g_sumsq2[i] = 0.f; }
    if (i == 0) g_total = 0;
}

// ---------------- count: histogram of right indices --------------------------
__global__ __launch_bounds__(256) void count_kernel(const int* __restrict__ idxR, int nE) {
    int i = blockIdx.x * blockDim.x + threadIdx.x;
    int stride = gridDim.x * blockDim.x;
    for (int e = i; e < nE; e += stride) atomicAdd(&g_cnt[idxR[e]], 1);
}

// ---------------- assign: contiguous segment offsets (order-free) ------------
__global__ __launch_bounds__(256) void assign_kernel(int nR) {
    int gtid = blockIdx.x * blockDim.x + threadIdx.x;
    int lane = threadIdx.x & 31;
    int stride = gridDim.x * blockDim.x;
    int niter = (nR + stride - 1) / stride;
    for (int it = 0; it < niter; it++) {
        int i = it * stride + gtid;
        int c = (i < nR) ? g_cnt[i] : 0;
        int s = c;
        #pragma unroll
        for (int d = 1; d < 32; d <<= 1) {
            int t = __shfl_up_sync(0xffffffffu, s, d);
            if (lane >= d) s += t;
        }
        int warpTotal = __shfl_sync(0xffffffffu, s, 31);
        int base = 0;
        if (lane == 31) base = atomicAdd(&g_total, warpTotal);
        base = __shfl_sync(0xffffffffu, base, 31);
        int off = base + s - c;
        if (i < nR) { g_off[i] = off; g_cur[i] = off; }
    }
}

// ---------------- bin: place {li, f} and r into per-node segments ------------
__global__ __launch_bounds__(256) void bin_kernel(
    const int* __restrict__ idxL, const int* __restrict__ idxR,
    const float* __restrict__ ef, int nE)
{
    int i = blockIdx.x * blockDim.x + threadIdx.x;
    int stride = gridDim.x * blockDim.x;
    for (int e = i; e < nE; e += stride) {
        int r = idxR[e];
        int li = idxL[e];
        float f = ef[e];
        int pos = atomicAdd(&g_cur[r], 1);
        g_sorted[pos] = make_int2(li, __float_as_int(f));
        g_srtR[pos] = r;
    }
}

// ---------------- tiled projections: 64x64 tile, 8x4 micro-tile per thread ---
// Y[i][j] = sum_k X[i][k] * W[j][k] (+ bias[j]); both L and R in one launch.
#define PROJ_PAD 68     // padded row stride in floats (17 float4) -> conflict-free
__global__ __launch_bounds__(128) void proj_kernel(
    const float* __restrict__ XL, const float* __restrict__ WL, const float* __restrict__ bL,
    const float* __restrict__ XR, const float* __restrict__ WR,
    int nL, int nR, int nbL)
{
    bool isL = (int)blockIdx.x < nbL;
    const float* X = isL ? XL : XR;
    const float* W = isL ? WL : WR;
    float* Y = isL ? g_left_proj : g_right_proj;
    int n = isL ? nL : nR;
    int bid = isL ? blockIdx.x : blockIdx.x - nbL;
    int rowBase = bid * 64;

    __shared__ float WT[64 * PROJ_PAD];   // WT[k][j] = W[j][k], padded
    __shared__ float XS[64 * PROJ_PAD];   // XS[r][k], padded
    __shared__ float bsh[EMB];
    for (int i = threadIdx.x; i < EMB * EMB; i += blockDim.x) {
        int j = i >> 6, k = i & 63;
        WT[k * PROJ_PAD + j] = W[i];
    }
    if (threadIdx.x < EMB) bsh[threadIdx.x] = isL ? bL[threadIdx.x] : 0.f;
    // load X tile (64 rows x 64 floats) as float4, zero-fill past n
    {
        const float4* X4 = (const float4*)X;
        #pragma unroll
        for (int it = 0; it < 8; it++) {
            int idx = it * 128 + threadIdx.x;       // 1024 float4 total
            int r = idx >> 4, k4 = idx & 15;
            int row = rowBase + r;
            float4 v = (row < n) ? X4[(size_t)row * 16 + k4]
                                 : make_float4(0.f, 0.f, 0.f, 0.f);
            *(float4*)(XS + r * PROJ_PAD + k4 * 4) = v;
        }
    }
    __syncthreads();

    int c16 = threadIdx.x & 15;     // column group: cols [4*c16, 4*c16+3]
    int rg  = threadIdx.x >> 4;     // row group: rows [8*rg, 8*rg+7]
    float4 b4 = ((const float4*)bsh)[c16];
    float4 acc[8];
    #pragma unroll
    for (int rr = 0; rr < 8; rr++) acc[rr] = b4;

    #pragma unroll 4
    for (int k4 = 0; k4 < 16; k4++) {
        float4 wf[4];
        #pragma unroll
        for (int kk = 0; kk < 4; kk++)
            wf[kk] = *(const float4*)(WT + (k4 * 4 + kk) * PROJ_PAD + c16 * 4);
        #pragma unroll
        for (int rr = 0; rr < 8; rr++) {
            float4 xf = *(const float4*)(XS + (rg * 8 + rr) * PROJ_PAD + k4 * 4);
            acc[rr].x = fmaf(xf.x, wf[0].x, acc[rr].x);
            acc[rr].y = fmaf(xf.x, wf[0].y, acc[rr].y);
            acc[rr].z = fmaf(xf.x, wf[0].z, acc[rr].z);
            acc[rr].w = fmaf(xf.x, wf[0].w, acc[rr].w);
            acc[rr].x = fmaf(xf.y, wf[1].x, acc[rr].x);
            acc[rr].y = fmaf(xf.y, wf[1].y, acc[rr].y);
            acc[rr].z = fmaf(xf.y, wf[1].z, acc[rr].z);
            acc[rr].w = fmaf(xf.y, wf[1].w, acc[rr].w);
            acc[rr].x = fmaf(xf.z, wf[2].x, acc[rr].x);
            acc[rr].y = fmaf(xf.z, wf[2].y, acc[rr].y);
            acc[rr].z = fmaf(xf.z, wf[2].z, acc[rr].z);
            acc[rr].w = fmaf(xf.z, wf[2].w, acc[rr].w);
            acc[rr].x = fmaf(xf.w, wf[3].x, acc[rr].x);
            acc[rr].y = fmaf(xf.w, wf[3].y, acc[rr].y);
            acc[rr].z = fmaf(xf.w, wf[3].z, acc[rr].z);
            acc[rr].w = fmaf(xf.w, wf[3].w, acc[rr].w);
        }
    }

    float4* Y4 = (float4*)Y;
    #pragma unroll
    for (int rr = 0; rr < 8; rr++) {
        int row = rowBase + rg * 8 + rr;
        if (row < n) Y4[(size_t)row * 16 + c16] = acc[rr];
    }
}

// ---------------- BN1 stats: chunked over original edges (order-free) --------
__global__ __launch_bounds__(256) void stats_kernel(
    const int* __restrict__ idxL, const int* __restrict__ idxR,
    const float* __restrict__ ef, const float* __restrict__ Wedge, int nE)
{
    int lane = threadIdx.x & 31;
    int hl = lane & 15;
    unsigned hmask = (lane & 16) ? 0xFFFF0000u : 0x0000FFFFu;
    int grp = (blockIdx.x * blockDim.x + threadIdx.x) >> 4;
    int ngrp = (gridDim.x * blockDim.x) >> 4;
    float4 we = ((const float4*)Wedge)[hl];
    float4 s = make_float4(0.f, 0.f, 0.f, 0.f);
    float4 sq = make_float4(0.f, 0.f, 0.f, 0.f);
    const float4* LP = (const float4*)g_left_proj;
    const float4* RP = (const float4*)g_right_proj;

    int nfull = nE >> 4;
    for (int ch = grp; ch < nfull; ch += ngrp) {
        int e = (ch << 4) + hl;
        int li = idxL[e], ri = idxR[e];
        float f = ef[e];
        #pragma unroll
        for (int j = 0; j < 16; j++) {
            int lj   = __shfl_sync(hmask, li, j, 16);
            int rj   = __shfl_sync(hmask, ri, j, 16);
            float fj = __shfl_sync(hmask, f, j, 16);
            float4 lp = LP[(size_t)lj * 16 + hl];
            float4 rp = RP[(size_t)rj * 16 + hl];
            float x;
            x = fmaf(fj, we.x, lp.x + rp.x); s.x += x; sq.x = fmaf(x, x, sq.x);
            x = fmaf(fj, we.y, lp.y + rp.y); s.y += x; sq.y = fmaf(x, x, sq.y);
            x = fmaf(fj, we.z, lp.z + rp.z); s.z += x; sq.z = fmaf(x, x, sq.z);
            x = fmaf(fj, we.w, lp.w + rp.w); s.w += x; sq.w = fmaf(x, x, sq.w);
        }
    }
    if (grp == 0) {
        for (int e = nfull << 4; e < nE; e++) {
            int lj = idxL[e], rj = idxR[e];
            float fj = ef[e];
            float4 lp = LP[(size_t)lj * 16 + hl];
            float4 rp = RP[(size_t)rj * 16 + hl];
            float x;
            x = fmaf(fj, we.x, lp.x + rp.x); s.x += x; sq.x = fmaf(x, x, sq.x);
            x = fmaf(fj, we.y, lp.y + rp.y); s.y += x; sq.y = fmaf(x, x, sq.y);
            x = fmaf(fj, we.z, lp.z + rp.z); s.z += x; sq.z = fmaf(x, x, sq.z);
            x = fmaf(fj, we.w, lp.w + rp.w); s.w += x; sq.w = fmaf(x, x, sq.w);
        }
    }
    s.x += __shfl_xor_sync(0xffffffffu, s.x, 16);
    s.y += __shfl_xor_sync(0xffffffffu, s.y, 16);
    s.z += __shfl_xor_sync(0xffffffffu, s.z, 16);
    s.w += __shfl_xor_sync(0xffffffffu, s.w, 16);
    sq.x += __shfl_xor_sync(0xffffffffu, sq.x, 16);
    sq.y += __shfl_xor_sync(0xffffffffu, sq.y, 16);
    sq.z += __shfl_xor_sync(0xffffffffu, sq.z, 16);
    sq.w += __shfl_xor_sync(0xffffffffu, sq.w, 16);

    __shared__ float cs[EMB], cq[EMB];
    if (threadIdx.x < EMB) { cs[threadIdx.x] = 0.f; cq[threadIdx.x] = 0.f; }
    __syncthreads();
    if (lane < 16) {
        atomicAdd(&cs[4 * hl + 0], s.x);
        atomicAdd(&cs[4 * hl + 1], s.y);
        atomicAdd(&cs[4 * hl + 2], s.z);
        atomicAdd(&cs[4 * hl + 3], s.w);
        atomicAdd(&cq[4 * hl + 0], sq.x);
        atomicAdd(&cq[4 * hl + 1], sq.y);
        atomicAdd(&cq[4 * hl + 2], sq.z);
        atomicAdd(&cq[4 * hl + 3], sq.w);
    }
    __syncthreads();
    if (threadIdx.x < EMB) {
        atomicAdd(&g_sum1[threadIdx.x], cs[threadIdx.x]);
        atomicAdd(&g_sumsq1[threadIdx.x], cq[threadIdx.x]);
    }
}

// ---------------- BN finalize ------------------------------------------------
__global__ void bn_fin_kernel(const float* __restrict__ sum, const float* __restrict__ sumsq,
                              const float* __restrict__ gamma, const float* __restrict__ beta,
                              float* __restrict__ scale, float* __restrict__ shift, float invN)
{
    int c = threadIdx.x;
    if (c < EMB) {
        float m = sum[c] * invN;
        float v = sumsq[c] * invN - m * m;
        float sc = gamma[c] * rsqrtf(v + BN_EPS);
        scale[c] = sc;
        shift[c] = beta[c] - m * sc;
    }
}

// ---------------- seg: chunked over sorted edges, run-length accumulate ------
__global__ __launch_bounds__(256) void seg_kernel(const float* __restrict__ Wedge, int nE)
{
    int lane = threadIdx.x & 31;
    int hl = lane & 15;
    unsigned hmask = (lane & 16) ? 0xFFFF0000u : 0x0000FFFFu;
    int grp = (blockIdx.x * blockDim.x + threadIdx.x) >> 4;
    int ngrp = (gridDim.x * blockDim.x) >> 4;
    float4 we = ((const float4*)Wedge)[hl];
    float4 sc = ((const float4*)g_scale1)[hl];
    float4 sh = ((const float4*)g_shift1)[hl];
    const float4* LP = (const float4*)g_left_proj;
    const float4* RP = (const float4*)g_right_proj;
    float4* Sv = (float4*)g_S;

    int nfull = nE >> 4;
    for (int ch = grp; ch < nfull; ch += ngrp) {
        int e = (ch << 4) + hl;
        int2 a = g_sorted[e];
        int r = g_srtR[e];
        int li = a.x;
        float f = __int_as_float(a.y);
        float4 acc = make_float4(0.f, 0.f, 0.f, 0.f);
        float4 rpv = make_float4(0.f, 0.f, 0.f, 0.f);
        int rprev = -1;
        #pragma unroll
        for (int j = 0; j < 16; j++) {
            int rj   = __shfl_sync(hmask, r, j, 16);
            int lj   = __shfl_sync(hmask, li, j, 16);
            float fj = __shfl_sync(hmask, f, j, 16);
            if (rj != rprev) {
                if (rprev >= 0) atomicAdd(&Sv[(size_t)rprev * 16 + hl], acc);
                rpv = RP[(size_t)rj * 16 + hl];
                acc = make_float4(0.f, 0.f, 0.f, 0.f);
                rprev = rj;
            }
            float4 lp = LP[(size_t)lj * 16 + hl];
            float x;
            x = fmaf(fj, we.x, lp.x + rpv.x); acc.x += fmaxf(fmaf(x, sc.x, sh.x), 0.f);
            x = fmaf(fj, we.y, lp.y + rpv.y); acc.y += fmaxf(fmaf(x, sc.y, sh.y), 0.f);
            x = fmaf(fj, we.z, lp.z + rpv.z); acc.z += fmaxf(fmaf(x, sc.z, sh.z), 0.f);
            x = fmaf(fj, we.w, lp.w + rpv.w); acc.w += fmaxf(fmaf(x, sc.w, sh.w), 0.f);
        }
        if (rprev >= 0) atomicAdd(&Sv[(size_t)rprev * 16 + hl], acc);
    }
    if (grp == 0) {
        for (int e = nfull << 4; e < nE; e++) {
            int2 a = g_sorted[e];
            int rj = g_srtR[e];
            float4 lp = LP[(size_t)a.x * 16 + hl];
            float4 rp = RP[(size_t)rj * 16 + hl];
            float fj = __int_as_float(a.y);
            float4 y;
            float x;
            x = fmaf(fj, we.x, lp.x + rp.x); y.x = fmaxf(fmaf(x, sc.x, sh.x), 0.f);
            x = fmaf(fj, we.y, lp.y + rp.y); y.y = fmaxf(fmaf(x, sc.y, sh.y), 0.f);
            x = fmaf(fj, we.z, lp.z + rp.z); y.z = fmaxf(fmaf(x, sc.z, sh.z), 0.f);
            x = fmaf(fj, we.w, lp.w + rp.w); y.w = fmaxf(fmaf(x, sc.w, sh.w), 0.f);
            atomicAdd(&Sv[(size_t)rj * 16 + hl], y);
        }
    }
}

// ---------------- conv = S @ Wf^T + cnt*b, fused BN2 column stats ------------
__global__ __launch_bounds__(128) void conv_stats_kernel(
    const float* __restrict__ X, const float* __restrict__ W,
    const float* __restrict__ bias, float* __restrict__ Y, int n)
{
    __shared__ float WT[EMB * EMB];
    __shared__ float bsh[EMB];
    __shared__ float cs[EMB], cq[EMB];
    for (int i = threadIdx.x; i < EMB * EMB; i += blockDim.x) {
        int j = i >> 6, k = i & 63;
        WT[k * EMB + j] = W[i];
    }
    if (threadIdx.x < EMB) {
        bsh[threadIdx.x] = bias[threadIdx.x];
        cs[threadIdx.x] = 0.f;
        cq[threadIdx.x] = 0.f;
    }
    __syncthreads();

    int row = blockIdx.x * blockDim.x + threadIdx.x;
    int lane = threadIdx.x & 31;
    bool valid = row < n;
    float acc[EMB];
    if (valid) {
        float bs = (float)g_cnt[row];
        #pragma unroll
        for (int j = 0; j < EMB; j++) acc[j] = bsh[j] * bs;
        const float4* Xr = (const float4*)(X + (size_t)row * EMB);
        #pragma unroll 2
        for (int k4 = 0; k4 < EMB / 4; k4++) {
            float4 xv = Xr[k4];
            const float* wp = &WT[(k4 * 4) * EMB];
            #pragma unroll
            for (int j = 0; j < EMB; j++) acc[j] = fmaf(wp[j], xv.x, acc[j]);
            #pragma unroll
            for (int j = 0; j < EMB; j++) acc[j] = fmaf(wp[EMB + j], xv.y, acc[j]);
            #pragma unroll
            for (int j = 0; j < EMB; j++) acc[j] = fmaf(wp[2 * EMB + j], xv.z, acc[j]);
            #pragma unroll
            for (int j = 0; j < EMB; j++) acc[j] = fmaf(wp[3 * EMB + j], xv.w, acc[j]);
        }
        float4* Yr = (float4*)(Y + (size_t)row * EMB);
        #pragma unroll
        for (int q = 0; q < EMB / 4; q++)
            Yr[q] = make_float4(acc[4 * q], acc[4 * q + 1], acc[4 * q + 2], acc[4 * q + 3]);
    } else {
        #pragma unroll
        for (int j = 0; j < EMB; j++) acc[j] = 0.f;
    }
    #pragma unroll
    for (int j = 0; j < EMB; j++) {
        float v = acc[j];
        float v2 = v * v;
        #pragma unroll
        for (int o = 16; o; o >>= 1) {
            v  += __shfl_xor_sync(0xffffffffu, v, o);
            v2 += __shfl_xor_sync(0xffffffffu, v2, o);
        }
        if (lane == 0) { atomicAdd(&cs[j], v); atomicAdd(&cq[j], v2); }
    }
    __syncthreads();
    if (threadIdx.x < EMB) {
        atomicAdd(&g_sum2[threadIdx.x], cs[threadIdx.x]);
        atomicAdd(&g_sumsq2[threadIdx.x], cq[threadIdx.x]);
    }
}

// ---------------- final: bn2 + concat + 2-layer MLP --------------------------
__global__ __launch_bounds__(128) void final_kernel(
    const float* __restrict__ right,
    const float* __restrict__ W1, const float* __restrict__ b1,
    const float* __restrict__ W2, const float* __restrict__ b2,
    float* __restrict__ out, int nR)
{
    __shared__ float Wsh[2 * EMB * EMB];
    __shared__ float sb[EMB], ssc[EMB], ssh[EMB];
    for (int i = threadIdx.x; i < 2 * EMB * EMB; i += blockDim.x) {
        int j = i >> 7, c = i & 127;       // W1 is [64,128]
        Wsh[c * EMB + j] = W1[i];
    }
    if (threadIdx.x < EMB) {
        sb[threadIdx.x] = b1[threadIdx.x];
        ssc[threadIdx.x] = g_scale2[threadIdx.x];
        ssh[threadIdx.x] = g_shift2[threadIdx.x];
    }
    __syncthreads();

    int row = blockIdx.x * blockDim.x + threadIdx.x;
    float h[EMB];
    if (row < nR) {
        #pragma unroll
        for (int j = 0; j < EMB; j++) h[j] = sb[j];
        const float4* cv = (const float4*)(g_conv + (size_t)row * EMB);
        #pragma unroll 2
        for (int k4 = 0; k4 < 16; k4++) {
            float4 v = cv[k4];
            int c = k4 * 4;
            float x0 = fmaf(v.x, ssc[c], ssh[c]);
            float x1 = fmaf(v.y, ssc[c + 1], ssh[c + 1]);
            float x2 = fmaf(v.z, ssc[c + 2], ssh[c + 2]);
            float x3 = fmaf(v.w, ssc[c + 3], ssh[c + 3]);
            const float* wp = &Wsh[c * EMB];
            #pragma unroll
            for (int j = 0; j < EMB; j++) h[j] = fmaf(wp[j], x0, h[j]);
            #pragma unroll
            for (int j = 0; j < EMB; j++) h[j] = fmaf(wp[EMB + j], x1, h[j]);
            #pragma unroll
            for (int j = 0; j < EMB; j++) h[j] = fmaf(wp[2 * EMB + j], x2, h[j]);
            #pragma unroll
            for (int j = 0; j < EMB; j++) h[j] = fmaf(wp[3 * EMB + j], x3, h[j]);
        }
        const float4* rf = (const float4*)(right + (size_t)row * EMB);
        #pragma unroll 2
        for (int k4 = 0; k4 < 16; k4++) {
            float4 v = rf[k4];
            int c = 64 + k4 * 4;
            const float* wp = &Wsh[c * EMB];
            #pragma unroll
            for (int j = 0; j < EMB; j++) h[j] = fmaf(wp[j], v.x, h[j]);
            #pragma unroll
            for (int j = 0; j < EMB; j++) h[j] = fmaf(wp[EMB + j], v.y, h[j]);
            #pragma unroll
            for (int j = 0; j < EMB; j++) h[j] = fmaf(wp[2 * EMB + j], v.z, h[j]);
            #pragma unroll
            for (int j = 0; j < EMB; j++) h[j] = fmaf(wp[3 * EMB + j], v.w, h[j]);
        }
        #pragma unroll
        for (int j = 0; j < EMB; j++) h[j] = fmaxf(h[j], 0.f);
    }
    __syncthreads();
    for (int i = threadIdx.x; i < EMB * EMB; i += blockDim.x) {
        int j = i >> 6, c = i & 63;
        Wsh[c * EMB + j] = W2[i];
    }
    if (threadIdx.x < EMB) sb[threadIdx.x] = b2[threadIdx.x];
    __syncthreads();
    if (row < nR) {
        float* orow = out + (size_t)row * EMB;
        #pragma unroll
        for (int jb = 0; jb < 4; jb++) {
            float acc[16];
            #pragma unroll
            for (int j = 0; j < 16; j++) acc[j] = sb[jb * 16 + j];
            #pragma unroll 4
            for (int c = 0; c < EMB; c++) {
                float hc = h[c];
                const float* wp = &Wsh[c * EMB + jb * 16];
                #pragma unroll
                for (int j = 0; j < 16; j++) acc[j] = fmaf(wp[j], hc, acc[j]);
            }
            float4* o4 = (float4*)(orow + jb * 16);
            #pragma unroll
            for (int q = 0; q < 4; q++)
                o4[q] = make_float4(fmaxf(acc[4 * q], 0.f), fmaxf(acc[4 * q + 1], 0.f),
                                    fmaxf(acc[4 * q + 2], 0.f), fmaxf(acc[4 * q + 3], 0.f));
        }
    }
}

// ---------------- launch -----------------------------------------------------
extern "C" void kernel_launch(void* const* d_in, const int* in_sizes, int n_in,
                              void* d_out, int out_size)
{
    const float* left  = (const float*)d_in[0];
    const int*   eidx  = (const int*)d_in[1];
    const float* ef    = (const float*)d_in[2];
    const float* right = (const float*)d_in[3];
    int off = (n_in >= 19) ? 1 : 0;
    const float* W_left    = (const float*)d_in[4 + off];
    const float* b_left    = (const float*)d_in[5 + off];
    const float* W_edge    = (const float*)d_in[6 + off];
    const float* W_right   = (const float*)d_in[7 + off];
    const float* bn1_gamma = (const float*)d_in[8 + off];
    const float* bn1_beta  = (const float*)d_in[9 + off];
    const float* W_final   = (const float*)d_in[10 + off];
    const float* b_final   = (const float*)d_in[11 + off];
    const float* bn2_gamma = (const float*)d_in[12 + off];
    const float* bn2_beta  = (const float*)d_in[13 + off];
    const float* W_out1    = (const float*)d_in[14 + off];
    const float* b_out1    = (const float*)d_in[15 + off];
    const float* W_out2    = (const float*)d_in[16 + off];
    const float* b_out2    = (const float*)d_in[17 + off];
    float* out = (float*)d_out;

    int nL = in_sizes[0] / EMB;
    int nE = in_sizes[2];
    int nR = in_sizes[3] / EMB;

    float* Sp; cudaGetSymbolAddress((void**)&Sp, g_S);
    float* cp; cudaGetSymbolAddress((void**)&cp, g_conv);
    float* s1; cudaGetSymbolAddress((void**)&s1, g_sum1);
    float* q1; cudaGetSymbolAddress((void**)&q1, g_sumsq1);
    float* sc1; cudaGetSymbolAddress((void**)&sc1, g_scale1);
    float* sh1; cudaGetSymbolAddress((void**)&sh1, g_shift1);
    float* s2; cudaGetSymbolAddress((void**)&s2, g_sum2);
    float* q2; cudaGetSymbolAddress((void**)&q2, g_sumsq2);
    float* sc2; cudaGetSymbolAddress((void**)&sc2, g_scale2);
    float* sh2; cudaGetSymbolAddress((void**)&sh2, g_shift2);

    int nbL = (nL + 63) / 64;
    int nbR = (nR + 63) / 64;
    int nbRrow = (nR + 127) / 128;

    // idx 0) zero counters/stats/S
    zero_kernel<<<1024, 256>>>(nR, nR * EMB);
    // idx 1) tiled projections (both matrices)
    proj_kernel<<<nbL + nbR, 128>>>(left, W_left, b_left, right, W_right, nL, nR, nbL);
    // idx 2) degree histogram
    count_kernel<<<1184, 256>>>(eidx + nE, nE);
    // idx 3) BN1 stats (chunked, original order)   <- profiled launch (index 3)
    stats_kernel<<<1184, 256>>>(eidx, eidx + nE, ef, W_edge, nE);
    // idx 4) contiguous segment offsets
    assign_kernel<<<(nR + 255) / 256, 256>>>(nR);
    // idx 5) bin {left_idx, f, r} into segments
    bin_kernel<<<1184, 256>>>(eidx, eidx + nE, ef, nE);
    // idx 6) BN1 finalize
    bn_fin_kernel<<<1, EMB>>>(s1, q1, bn1_gamma, bn1_beta, sc1, sh1, 1.0f / (float)nE);
    // idx 7) segment sum over sorted edges, run-length accumulated
    seg_kernel<<<1184, 256>>>(W_edge, nE);
    // idx 8) conv = S @ W_final^T + cnt * b_final, fused BN2 stats
    conv_stats_kernel<<<nbRrow, 128>>>(Sp, W_final, b_final, cp, nR);
    // idx 9) BN2 finalize
    bn_fin_kernel<<<1, EMB>>>(s2, q2, bn2_gamma, bn2_beta, sc2, sh2, 1.0f / (float)nR);
    // idx 10) final MLP
    final_kernel<<<nbRrow, 128>>>(right, W_out1, b_out1, W_out2, b_out2, out, nR);
}

// round 8
// speedup vs baseline: 1.1544x; 1.1029x over previous
#include <cuda_runtime.h>
#include <cuda_bf16.h>

#define EMB 64
#define BN_EPS 1e-5f
#define MAX_L 50000
#define MAX_R 100000
#define MAX_E 1100000

typedef unsigned long long ull;

// ---------------- f32x2 packed-FMA helpers (FFMA2; ptxas never emits these) --
__device__ __forceinline__ ull pk2(float lo, float hi) {
    ull r; asm("mov.b64 %0, {%1, %2};" : "=l"(r) : "f"(lo), "f"(hi)); return r;
}
__device__ __forceinline__ float2 up2(ull v) {
    float2 f; asm("mov.b64 {%0, %1}, %2;" : "=f"(f.x), "=f"(f.y) : "l"(v)); return f;
}
__device__ __forceinline__ ull fma2(ull a, ull b, ull c) {
    ull d; asm("fma.rn.f32x2 %0, %1, %2, %3;" : "=l"(d) : "l"(a), "l"(b), "l"(c)); return d;
}

// ---------------- scratch (static device globals; no allocation) -------------
__device__ float g_left_proj[MAX_L * EMB];
__device__ float g_right_proj[MAX_R * EMB];
__device__ float g_S[MAX_R * EMB];
__device__ float g_conv[MAX_R * EMB];
__device__ int   g_cnt[MAX_R];
__device__ int   g_off[MAX_R];
__device__ int   g_cur[MAX_R];
__device__ int   g_total;
__device__ int2  g_sorted[MAX_E];
__device__ int   g_srtR[MAX_E];
__device__ float g_sum1[EMB], g_sumsq1[EMB], g_scale1[EMB], g_shift1[EMB];
__device__ float g_sum2[EMB], g_sumsq2[EMB], g_scale2[EMB], g_shift2[EMB];

// ---------------- zero scratch ----------------------------------------------
__global__ void zero_kernel(int nR, int nS) {
    int i = blockIdx.x * blockDim.x + threadIdx.x;
    int stride = gridDim.x * blockDim.x;
    for (int k = i; k < nR; k += stride) g_cnt[k] = 0;
    for (int k = i; k < nS; k += stride) g_S[k] = 0.f;
    if (i < EMB) { g_sum1[i] = 0.f; g_sumsq1[i] = 0.f; g_sum2[i] = 0.f; g_sumsq2[i] = 0.f; }
    if (i == 0) g_total = 0;
}

// ---------------- count: histogram of right indices --------------------------
__global__ __launch_bounds__(256) void count_kernel(const int* __restrict__ idxR, int nE) {
    int i = blockIdx.x * blockDim.x + threadIdx.x;
    int stride = gridDim.x * blockDim.x;
    for (int e = i; e < nE; e += stride) atomicAdd(&g_cnt[idxR[e]], 1);
}

// ---------------- assign: contiguous segment offsets (order-free) ------------
__global__ __launch_bounds__(256) void assign_kernel(int nR) {
    int gtid = blockIdx.x * blockDim.x + threadIdx.x;
    int lane = threadIdx.x & 31;
    int stride = gridDim.x * blockDim.x;
    int niter = (nR + stride - 1) / stride;
    for (int it = 0; it < niter; it++) {
        int i = it * stride + gtid;
        int c = (i < nR) ? g_cnt[i] : 0;
        int s = c;
        #pragma unroll
        for (int d = 1; d < 32; d <<= 1) {
            int t = __shfl_up_sync(0xffffffffu, s, d);
            if (lane >= d) s += t;
        }
        int warpTotal = __shfl_sync(0xffffffffu, s, 31);
        int base = 0;
        if (lane == 31) base = atomicAdd(&g_total, warpTotal);
        base = __shfl_sync(0xffffffffu, base, 31);
        int off = base + s - c;
        if (i < nR) { g_off[i] = off; g_cur[i] = off; }
    }
}

// ---------------- bin: place {li, f} and r into per-node segments ------------
__global__ __launch_bounds__(256) void bin_kernel(
    const int* __restrict__ idxL, const int* __restrict__ idxR,
    const float* __restrict__ ef, int nE)
{
    int i = blockIdx.x * blockDim.x + threadIdx.x;
    int stride = gridDim.x * blockDim.x;
    for (int e = i; e < nE; e += stride) {
        int r = idxR[e];
        int li = idxL[e];
        float f = ef[e];
        int pos = atomicAdd(&g_cur[r], 1);
        g_sorted[pos] = make_int2(li, __float_as_int(f));
        g_srtR[pos] = r;
    }
}

// ---------------- tiled projections (f32x2): 64x64 tile, 8x4 per thread ------
#define PROJ_PAD 68
__global__ __launch_bounds__(128) void proj_kernel(
    const float* __restrict__ XL, const float* __restrict__ WL, const float* __restrict__ bL,
    const float* __restrict__ XR, const float* __restrict__ WR,
    int nL, int nR, int nbL)
{
    bool isL = (int)blockIdx.x < nbL;
    const float* X = isL ? XL : XR;
    const float* W = isL ? WL : WR;
    float* Y = isL ? g_left_proj : g_right_proj;
    int n = isL ? nL : nR;
    int bid = isL ? blockIdx.x : blockIdx.x - nbL;
    int rowBase = bid * 64;

    __shared__ float WT[64 * PROJ_PAD];   // WT[k][j] = W[j][k]
    __shared__ float XS[64 * PROJ_PAD];
    __shared__ float bsh[EMB];
    for (int i = threadIdx.x; i < EMB * EMB; i += blockDim.x) {
        int j = i >> 6, k = i & 63;
        WT[k * PROJ_PAD + j] = W[i];
    }
    if (threadIdx.x < EMB) bsh[threadIdx.x] = isL ? bL[threadIdx.x] : 0.f;
    {
        const float4* X4 = (const float4*)X;
        #pragma unroll
        for (int it = 0; it < 8; it++) {
            int idx = it * 128 + threadIdx.x;
            int r = idx >> 4, k4 = idx & 15;
            int row = rowBase + r;
            float4 v = (row < n) ? X4[(size_t)row * 16 + k4]
                                 : make_float4(0.f, 0.f, 0.f, 0.f);
            *(float4*)(XS + r * PROJ_PAD + k4 * 4) = v;
        }
    }
    __syncthreads();

    int c16 = threadIdx.x & 15;
    int rg  = threadIdx.x >> 4;
    float4 b4 = ((const float4*)bsh)[c16];
    ull acc0[8], acc1[8];
    #pragma unroll
    for (int rr = 0; rr < 8; rr++) { acc0[rr] = pk2(b4.x, b4.y); acc1[rr] = pk2(b4.z, b4.w); }

    #pragma unroll 2
    for (int k4 = 0; k4 < 16; k4++) {
        ulonglong2 w2[4];
        #pragma unroll
        for (int kk = 0; kk < 4; kk++)
            w2[kk] = *(const ulonglong2*)(WT + (k4 * 4 + kk) * PROJ_PAD + c16 * 4);
        #pragma unroll
        for (int rr = 0; rr < 8; rr++) {
            float4 xf = *(const float4*)(XS + (rg * 8 + rr) * PROJ_PAD + k4 * 4);
            ull xp;
            xp = pk2(xf.x, xf.x); acc0[rr] = fma2(xp, w2[0].x, acc0[rr]); acc1[rr] = fma2(xp, w2[0].y, acc1[rr]);
            xp = pk2(xf.y, xf.y); acc0[rr] = fma2(xp, w2[1].x, acc0[rr]); acc1[rr] = fma2(xp, w2[1].y, acc1[rr]);
            xp = pk2(xf.z, xf.z); acc0[rr] = fma2(xp, w2[2].x, acc0[rr]); acc1[rr] = fma2(xp, w2[2].y, acc1[rr]);
            xp = pk2(xf.w, xf.w); acc0[rr] = fma2(xp, w2[3].x, acc0[rr]); acc1[rr] = fma2(xp, w2[3].y, acc1[rr]);
        }
    }

    float4* Y4 = (float4*)Y;
    #pragma unroll
    for (int rr = 0; rr < 8; rr++) {
        int row = rowBase + rg * 8 + rr;
        if (row < n) {
            float2 a = up2(acc0[rr]), b = up2(acc1[rr]);
            Y4[(size_t)row * 16 + c16] = make_float4(a.x, a.y, b.x, b.y);
        }
    }
}

// ---------------- BN1 stats: chunked over original edges ---------------------
__global__ __launch_bounds__(256) void stats_kernel(
    const int* __restrict__ idxL, const int* __restrict__ idxR,
    const float* __restrict__ ef, const float* __restrict__ Wedge, int nE)
{
    int lane = threadIdx.x & 31;
    int hl = lane & 15;
    unsigned hmask = (lane & 16) ? 0xFFFF0000u : 0x0000FFFFu;
    int grp = (blockIdx.x * blockDim.x + threadIdx.x) >> 4;
    int ngrp = (gridDim.x * blockDim.x) >> 4;
    float4 we = ((const float4*)Wedge)[hl];
    float4 s = make_float4(0.f, 0.f, 0.f, 0.f);
    float4 sq = make_float4(0.f, 0.f, 0.f, 0.f);
    const float4* LP = (const float4*)g_left_proj;
    const float4* RP = (const float4*)g_right_proj;

    int nfull = nE >> 4;
    for (int ch = grp; ch < nfull; ch += ngrp) {
        int e = (ch << 4) + hl;
        int li = idxL[e], ri = idxR[e];
        float f = ef[e];
        #pragma unroll
        for (int j = 0; j < 16; j++) {
            int lj   = __shfl_sync(hmask, li, j, 16);
            int rj   = __shfl_sync(hmask, ri, j, 16);
            float fj = __shfl_sync(hmask, f, j, 16);
            float4 lp = LP[(size_t)lj * 16 + hl];
            float4 rp = RP[(size_t)rj * 16 + hl];
            float x;
            x = fmaf(fj, we.x, lp.x + rp.x); s.x += x; sq.x = fmaf(x, x, sq.x);
            x = fmaf(fj, we.y, lp.y + rp.y); s.y += x; sq.y = fmaf(x, x, sq.y);
            x = fmaf(fj, we.z, lp.z + rp.z); s.z += x; sq.z = fmaf(x, x, sq.z);
            x = fmaf(fj, we.w, lp.w + rp.w); s.w += x; sq.w = fmaf(x, x, sq.w);
        }
    }
    if (grp == 0) {
        for (int e = nfull << 4; e < nE; e++) {
            int lj = idxL[e], rj = idxR[e];
            float fj = ef[e];
            float4 lp = LP[(size_t)lj * 16 + hl];
            float4 rp = RP[(size_t)rj * 16 + hl];
            float x;
            x = fmaf(fj, we.x, lp.x + rp.x); s.x += x; sq.x = fmaf(x, x, sq.x);
            x = fmaf(fj, we.y, lp.y + rp.y); s.y += x; sq.y = fmaf(x, x, sq.y);
            x = fmaf(fj, we.z, lp.z + rp.z); s.z += x; sq.z = fmaf(x, x, sq.z);
            x = fmaf(fj, we.w, lp.w + rp.w); s.w += x; sq.w = fmaf(x, x, sq.w);
        }
    }
    s.x += __shfl_xor_sync(0xffffffffu, s.x, 16);
    s.y += __shfl_xor_sync(0xffffffffu, s.y, 16);
    s.z += __shfl_xor_sync(0xffffffffu, s.z, 16);
    s.w += __shfl_xor_sync(0xffffffffu, s.w, 16);
    sq.x += __shfl_xor_sync(0xffffffffu, sq.x, 16);
    sq.y += __shfl_xor_sync(0xffffffffu, sq.y, 16);
    sq.z += __shfl_xor_sync(0xffffffffu, sq.z, 16);
    sq.w += __shfl_xor_sync(0xffffffffu, sq.w, 16);

    __shared__ float cs[EMB], cq[EMB];
    if (threadIdx.x < EMB) { cs[threadIdx.x] = 0.f; cq[threadIdx.x] = 0.f; }
    __syncthreads();
    if (lane < 16) {
        atomicAdd(&cs[4 * hl + 0], s.x);
        atomicAdd(&cs[4 * hl + 1], s.y);
        atomicAdd(&cs[4 * hl + 2], s.z);
        atomicAdd(&cs[4 * hl + 3], s.w);
        atomicAdd(&cq[4 * hl + 0], sq.x);
        atomicAdd(&cq[4 * hl + 1], sq.y);
        atomicAdd(&cq[4 * hl + 2], sq.z);
        atomicAdd(&cq[4 * hl + 3], sq.w);
    }
    __syncthreads();
    if (threadIdx.x < EMB) {
        atomicAdd(&g_sum1[threadIdx.x], cs[threadIdx.x]);
        atomicAdd(&g_sumsq1[threadIdx.x], cq[threadIdx.x]);
    }
}

// ---------------- BN finalize ------------------------------------------------
__global__ void bn_fin_kernel(const float* __restrict__ sum, const float* __restrict__ sumsq,
                              const float* __restrict__ gamma, const float* __restrict__ beta,
                              float* __restrict__ scale, float* __restrict__ shift, float invN)
{
    int c = threadIdx.x;
    if (c < EMB) {
        float m = sum[c] * invN;
        float v = sumsq[c] * invN - m * m;
        float sc = gamma[c] * rsqrtf(v + BN_EPS);
        scale[c] = sc;
        shift[c] = beta[c] - m * sc;
    }
}

// ---------------- seg: chunked over sorted edges, run-length accumulate ------
__global__ __launch_bounds__(256) void seg_kernel(const float* __restrict__ Wedge, int nE)
{
    int lane = threadIdx.x & 31;
    int hl = lane & 15;
    unsigned hmask = (lane & 16) ? 0xFFFF0000u : 0x0000FFFFu;
    int grp = (blockIdx.x * blockDim.x + threadIdx.x) >> 4;
    int ngrp = (gridDim.x * blockDim.x) >> 4;
    float4 we = ((const float4*)Wedge)[hl];
    float4 sc = ((const float4*)g_scale1)[hl];
    float4 sh = ((const float4*)g_shift1)[hl];
    const float4* LP = (const float4*)g_left_proj;
    const float4* RP = (const float4*)g_right_proj;
    float4* Sv = (float4*)g_S;

    int nfull = nE >> 4;
    for (int ch = grp; ch < nfull; ch += ngrp) {
        int e = (ch << 4) + hl;
        int2 a = g_sorted[e];
        int r = g_srtR[e];
        int li = a.x;
        float f = __int_as_float(a.y);
        float4 acc = make_float4(0.f, 0.f, 0.f, 0.f);
        float4 rpv = make_float4(0.f, 0.f, 0.f, 0.f);
        int rprev = -1;
        #pragma unroll
        for (int j = 0; j < 16; j++) {
            int rj   = __shfl_sync(hmask, r, j, 16);
            int lj   = __shfl_sync(hmask, li, j, 16);
            float fj = __shfl_sync(hmask, f, j, 16);
            if (rj != rprev) {
                if (rprev >= 0) atomicAdd(&Sv[(size_t)rprev * 16 + hl], acc);
                rpv = RP[(size_t)rj * 16 + hl];
                acc = make_float4(0.f, 0.f, 0.f, 0.f);
                rprev = rj;
            }
            float4 lp = LP[(size_t)lj * 16 + hl];
            float x;
            x = fmaf(fj, we.x, lp.x + rpv.x); acc.x += fmaxf(fmaf(x, sc.x, sh.x), 0.f);
            x = fmaf(fj, we.y, lp.y + rpv.y); acc.y += fmaxf(fmaf(x, sc.y, sh.y), 0.f);
            x = fmaf(fj, we.z, lp.z + rpv.z); acc.z += fmaxf(fmaf(x, sc.z, sh.z), 0.f);
            x = fmaf(fj, we.w, lp.w + rpv.w); acc.w += fmaxf(fmaf(x, sc.w, sh.w), 0.f);
        }
        if (rprev >= 0) atomicAdd(&Sv[(size_t)rprev * 16 + hl], acc);
    }
    if (grp == 0) {
        for (int e = nfull << 4; e < nE; e++) {
            int2 a = g_sorted[e];
            int rj = g_srtR[e];
            float4 lp = LP[(size_t)a.x * 16 + hl];
            float4 rp = RP[(size_t)rj * 16 + hl];
            float fj = __int_as_float(a.y);
            float4 y;
            float x;
            x = fmaf(fj, we.x, lp.x + rp.x); y.x = fmaxf(fmaf(x, sc.x, sh.x), 0.f);
            x = fmaf(fj, we.y, lp.y + rp.y); y.y = fmaxf(fmaf(x, sc.y, sh.y), 0.f);
            x = fmaf(fj, we.z, lp.z + rp.z); y.z = fmaxf(fmaf(x, sc.z, sh.z), 0.f);
            x = fmaf(fj, we.w, lp.w + rp.w); y.w = fmaxf(fmaf(x, sc.w, sh.w), 0.f);
            atomicAdd(&Sv[(size_t)rj * 16 + hl], y);
        }
    }
}

// ---------------- conv = S @ Wf^T + cnt*b (f32x2), fused BN2 stats -----------
__global__ __launch_bounds__(128) void conv_stats_kernel(
    const float* __restrict__ X, const float* __restrict__ W,
    const float* __restrict__ bias, float* __restrict__ Y, int n)
{
    __shared__ float WT[EMB * EMB];
    __shared__ float bsh[EMB];
    __shared__ float cs[EMB], cq[EMB];
    for (int i = threadIdx.x; i < EMB * EMB; i += blockDim.x) {
        int j = i >> 6, k = i & 63;
        WT[k * EMB + j] = W[i];
    }
    if (threadIdx.x < EMB) {
        bsh[threadIdx.x] = bias[threadIdx.x];
        cs[threadIdx.x] = 0.f;
        cq[threadIdx.x] = 0.f;
    }
    __syncthreads();

    int row = blockIdx.x * blockDim.x + threadIdx.x;
    int lane = threadIdx.x & 31;
    bool valid = row < n;
    float acc[EMB];
    if (valid) {
        float bs = (float)g_cnt[row];
        ull acc2[32];
        #pragma unroll
        for (int p = 0; p < 32; p++)
            acc2[p] = pk2(bsh[2 * p] * bs, bsh[2 * p + 1] * bs);
        const float4* Xr = (const float4*)(X + (size_t)row * EMB);
        #pragma unroll 2
        for (int k4 = 0; k4 < 16; k4++) {
            float4 xv = Xr[k4];
            float xs4[4] = {xv.x, xv.y, xv.z, xv.w};
            #pragma unroll
            for (int kk = 0; kk < 4; kk++) {
                ull xp = pk2(xs4[kk], xs4[kk]);
                const ulonglong2* wq = (const ulonglong2*)(WT + (k4 * 4 + kk) * EMB);
                #pragma unroll
                for (int p = 0; p < 16; p++) {
                    ulonglong2 w2 = wq[p];
                    acc2[2 * p]     = fma2(xp, w2.x, acc2[2 * p]);
                    acc2[2 * p + 1] = fma2(xp, w2.y, acc2[2 * p + 1]);
                }
            }
        }
        #pragma unroll
        for (int p = 0; p < 32; p++) {
            float2 f = up2(acc2[p]);
            acc[2 * p] = f.x;
            acc[2 * p + 1] = f.y;
        }
        float4* Yr = (float4*)(Y + (size_t)row * EMB);
        #pragma unroll
        for (int q = 0; q < EMB / 4; q++)
            Yr[q] = make_float4(acc[4 * q], acc[4 * q + 1], acc[4 * q + 2], acc[4 * q + 3]);
    } else {
        #pragma unroll
        for (int j = 0; j < EMB; j++) acc[j] = 0.f;
    }
    #pragma unroll
    for (int j = 0; j < EMB; j++) {
        float v = acc[j];
        float v2 = v * v;
        #pragma unroll
        for (int o = 16; o; o >>= 1) {
            v  += __shfl_xor_sync(0xffffffffu, v, o);
            v2 += __shfl_xor_sync(0xffffffffu, v2, o);
        }
        if (lane == 0) { atomicAdd(&cs[j], v); atomicAdd(&cq[j], v2); }
    }
    __syncthreads();
    if (threadIdx.x < EMB) {
        atomicAdd(&g_sum2[threadIdx.x], cs[threadIdx.x]);
        atomicAdd(&g_sumsq2[threadIdx.x], cq[threadIdx.x]);
    }
}

// ---------------- final: bn2 + concat + 2-layer MLP (f32x2) ------------------
__global__ __launch_bounds__(128) void final_kernel(
    const float* __restrict__ right,
    const float* __restrict__ W1, const float* __restrict__ b1,
    const float* __restrict__ W2, const float* __restrict__ b2,
    float* __restrict__ out, int nR)
{
    __shared__ float Wsh[2 * EMB * EMB];
    __shared__ float sb[EMB], ssc[EMB], ssh[EMB];
    for (int i = threadIdx.x; i < 2 * EMB * EMB; i += blockDim.x) {
        int j = i >> 7, c = i & 127;       // W1 is [64,128]
        Wsh[c * EMB + j] = W1[i];
    }
    if (threadIdx.x < EMB) {
        sb[threadIdx.x] = b1[threadIdx.x];
        ssc[threadIdx.x] = g_scale2[threadIdx.x];
        ssh[threadIdx.x] = g_shift2[threadIdx.x];
    }
    __syncthreads();

    int row = blockIdx.x * blockDim.x + threadIdx.x;
    float h[EMB];
    if (row < nR) {
        ull h2[32];
        #pragma unroll
        for (int p = 0; p < 32; p++) h2[p] = pk2(sb[2 * p], sb[2 * p + 1]);
        const float4* cv = (const float4*)(g_conv + (size_t)row * EMB);
        #pragma unroll 2
        for (int k4 = 0; k4 < 16; k4++) {
            float4 v = cv[k4];
            int c = k4 * 4;
            float xs4[4] = {
                fmaf(v.x, ssc[c], ssh[c]),
                fmaf(v.y, ssc[c + 1], ssh[c + 1]),
                fmaf(v.z, ssc[c + 2], ssh[c + 2]),
                fmaf(v.w, ssc[c + 3], ssh[c + 3]) };
            #pragma unroll
            for (int kk = 0; kk < 4; kk++) {
                ull xp = pk2(xs4[kk], xs4[kk]);
                const ulonglong2* wq = (const ulonglong2*)(Wsh + (c + kk) * EMB);
                #pragma unroll
                for (int p = 0; p < 16; p++) {
                    ulonglong2 w2 = wq[p];
                    h2[2 * p]     = fma2(xp, w2.x, h2[2 * p]);
                    h2[2 * p + 1] = fma2(xp, w2.y, h2[2 * p + 1]);
                }
            }
        }
        const float4* rf = (const float4*)(right + (size_t)row * EMB);
        #pragma unroll 2
        for (int k4 = 0; k4 < 16; k4++) {
            float4 v = rf[k4];
            int c = 64 + k4 * 4;
            float xs4[4] = {v.x, v.y, v.z, v.w};
            #pragma unroll
            for (int kk = 0; kk < 4; kk++) {
                ull xp = pk2(xs4[kk], xs4[kk]);
                const ulonglong2* wq = (const ulonglong2*)(Wsh + (c + kk) * EMB);
                #pragma unroll
                for (int p = 0; p < 16; p++) {
                    ulonglong2 w2 = wq[p];
                    h2[2 * p]     = fma2(xp, w2.x, h2[2 * p]);
                    h2[2 * p + 1] = fma2(xp, w2.y, h2[2 * p + 1]);
                }
            }
        }
        #pragma unroll
        for (int p = 0; p < 32; p++) {
            float2 f = up2(h2[p]);
            h[2 * p] = fmaxf(f.x, 0.f);
            h[2 * p + 1] = fmaxf(f.y, 0.f);
        }
    }
    __syncthreads();
    for (int i = threadIdx.x; i < EMB * EMB; i += blockDim.x) {
        int j = i >> 6, c = i & 63;
        Wsh[c * EMB + j] = W2[i];
    }
    if (threadIdx.x < EMB) sb[threadIdx.x] = b2[threadIdx.x];
    __syncthreads();
    if (row < nR) {
        float* orow = out + (size_t)row * EMB;
        #pragma unroll
        for (int jb = 0; jb < 4; jb++) {
            ull a2[8];
            #pragma unroll
            for (int q = 0; q < 8; q++)
                a2[q] = pk2(sb[jb * 16 + 2 * q], sb[jb * 16 + 2 * q + 1]);
            #pragma unroll 4
            for (int c = 0; c < EMB; c++) {
                ull xp = pk2(h[c], h[c]);
                const ulonglong2* wq = (const ulonglong2*)(Wsh + c * EMB + jb * 16);
                #pragma unroll
                for (int q = 0; q < 4; q++) {
                    ulonglong2 w2 = wq[q];
                    a2[2 * q]     = fma2(xp, w2.x, a2[2 * q]);
                    a2[2 * q + 1] = fma2(xp, w2.y, a2[2 * q + 1]);
                }
            }
            float4* o4 = (float4*)(orow + jb * 16);
            #pragma unroll
            for (int q = 0; q < 4; q++) {
                float2 f0 = up2(a2[2 * q]), f1 = up2(a2[2 * q + 1]);
                o4[q] = make_float4(fmaxf(f0.x, 0.f), fmaxf(f0.y, 0.f),
                                    fmaxf(f1.x, 0.f), fmaxf(f1.y, 0.f));
            }
        }
    }
}

// ---------------- launch -----------------------------------------------------
extern "C" void kernel_launch(void* const* d_in, const int* in_sizes, int n_in,
                              void* d_out, int out_size)
{
    const float* left  = (const float*)d_in[0];
    const int*   eidx  = (const int*)d_in[1];
    const float* ef    = (const float*)d_in[2];
    const float* right = (const float*)d_in[3];
    int off = (n_in >= 19) ? 1 : 0;
    const float* W_left    = (const float*)d_in[4 + off];
    const float* b_left    = (const float*)d_in[5 + off];
    const float* W_edge    = (const float*)d_in[6 + off];
    const float* W_right   = (const float*)d_in[7 + off];
    const float* bn1_gamma = (const float*)d_in[8 + off];
    const float* bn1_beta  = (const float*)d_in[9 + off];
    const float* W_final   = (const float*)d_in[10 + off];
    const float* b_final   = (const float*)d_in[11 + off];
    const float* bn2_gamma = (const float*)d_in[12 + off];
    const float* bn2_beta  = (const float*)d_in[13 + off];
    const float* W_out1    = (const float*)d_in[14 + off];
    const float* b_out1    = (const float*)d_in[15 + off];
    const float* W_out2    = (const float*)d_in[16 + off];
    const float* b_out2    = (const float*)d_in[17 + off];
    float* out = (float*)d_out;

    int nL = in_sizes[0] / EMB;
    int nE = in_sizes[2];
    int nR = in_sizes[3] / EMB;

    float* Sp; cudaGetSymbolAddress((void**)&Sp, g_S);
    float* cp; cudaGetSymbolAddress((void**)&cp, g_conv);
    float* s1; cudaGetSymbolAddress((void**)&s1, g_sum1);
    float* q1; cudaGetSymbolAddress((void**)&q1, g_sumsq1);
    float* sc1; cudaGetSymbolAddress((void**)&sc1, g_scale1);
    float* sh1; cudaGetSymbolAddress((void**)&sh1, g_shift1);
    float* s2; cudaGetSymbolAddress((void**)&s2, g_sum2);
    float* q2; cudaGetSymbolAddress((void**)&q2, g_sumsq2);
    float* sc2; cudaGetSymbolAddress((void**)&sc2, g_scale2);
    float* sh2; cudaGetSymbolAddress((void**)&sh2, g_shift2);

    int nbL = (nL + 63) / 64;
    int nbR = (nR + 63) / 64;
    int nbRrow = (nR + 127) / 128;

    // idx 0) zero counters/stats/S
    zero_kernel<<<1024, 256>>>(nR, nR * EMB);
    // idx 1) degree histogram
    count_kernel<<<1184, 256>>>(eidx + nE, nE);
    // idx 2) contiguous segment offsets
    assign_kernel<<<(nR + 255) / 256, 256>>>(nR);
    // idx 3) tiled projections (f32x2)             <- profiled launch (index 3)
    proj_kernel<<<nbL + nbR, 128>>>(left, W_left, b_left, right, W_right, nL, nR, nbL);
    // idx 4) bin {left_idx, f, r} into segments
    bin_kernel<<<1184, 256>>>(eidx, eidx + nE, ef, nE);
    // idx 5) BN1 stats (chunked, original order)
    stats_kernel<<<1184, 256>>>(eidx, eidx + nE, ef, W_edge, nE);
    // idx 6) BN1 finalize
    bn_fin_kernel<<<1, EMB>>>(s1, q1, bn1_gamma, bn1_beta, sc1, sh1, 1.0f / (float)nE);
    // idx 7) segment sum over sorted edges
    seg_kernel<<<1184, 256>>>(W_edge, nE);
    // idx 8) conv GEMM (f32x2) + fused BN2 stats
    conv_stats_kernel<<<nbRrow, 128>>>(Sp, W_final, b_final, cp, nR);
    // idx 9) BN2 finalize
    bn_fin_kernel<<<1, EMB>>>(s2, q2, bn2_gamma, bn2_beta, sc2, sh2, 1.0f / (float)nR);
    // idx 10) final MLP (f32x2)
    final_kernel<<<nbRrow, 128>>>(right, W_out1, b_out1, W_out2, b_out2, out, nR);
}

// round 10
// speedup vs baseline: 1.1734x; 1.0164x over previous
#include <cuda_runtime.h>
#include <cuda_bf16.h>

#define EMB 64
#define BN_EPS 1e-5f
#define MAX_L 50000
#define MAX_R 100000
#define MAX_E 1100000

typedef unsigned long long ull;

// ---------------- f32x2 packed-FMA helpers (FFMA2; ptxas never emits these) --
__device__ __forceinline__ ull pk2(float lo, float hi) {
    ull r; asm("mov.b64 %0, {%1, %2};" : "=l"(r) : "f"(lo), "f"(hi)); return r;
}
__device__ __forceinline__ float2 up2(ull v) {
    float2 f; asm("mov.b64 {%0, %1}, %2;" : "=f"(f.x), "=f"(f.y) : "l"(v)); return f;
}
__device__ __forceinline__ ull fma2(ull a, ull b, ull c) {
    ull d; asm("fma.rn.f32x2 %0, %1, %2, %3;" : "=l"(d) : "l"(a), "l"(b), "l"(c)); return d;
}

// ---------------- scratch (static device globals; no allocation) -------------
__device__ float g_left_proj[MAX_L * EMB];
__device__ float g_right_proj[MAX_R * EMB];
__device__ float g_S[MAX_R * EMB];
__device__ float g_conv[MAX_R * EMB];
__device__ int   g_cnt[MAX_R];
__device__ int   g_off[MAX_R];
__device__ int   g_cur[MAX_R];
__device__ int   g_total;
__device__ int2  g_sorted[MAX_E];
__device__ int   g_srtR[MAX_E];
__device__ float g_sum1[EMB], g_sumsq1[EMB], g_scale1[EMB], g_shift1[EMB];
__device__ float g_sum2[EMB], g_sumsq2[EMB], g_scale2[EMB], g_shift2[EMB];

// ---------------- zero scratch ----------------------------------------------
__global__ void zero_kernel(int nR, int nS) {
    int i = blockIdx.x * blockDim.x + threadIdx.x;
    int stride = gridDim.x * blockDim.x;
    for (int k = i; k < nR; k += stride) g_cnt[k] = 0;
    for (int k = i; k < nS; k += stride) g_S[k] = 0.f;
    if (i < EMB) { g_sum1[i] = 0.f; g_sumsq1[i] = 0.f; g_sum2[i] = 0.f; g_sumsq2[i] = 0.f; }
    if (i == 0) g_total = 0;
}

// ---------------- count: histogram of right indices --------------------------
__global__ __launch_bounds__(256) void count_kernel(const int* __restrict__ idxR, int nE) {
    int i = blockIdx.x * blockDim.x + threadIdx.x;
    int stride = gridDim.x * blockDim.x;
    for (int e = i; e < nE; e += stride) atomicAdd(&g_cnt[idxR[e]], 1);
}

// ---------------- assign: contiguous segment offsets (order-free) ------------
__global__ __launch_bounds__(256) void assign_kernel(int nR) {
    int gtid = blockIdx.x * blockDim.x + threadIdx.x;
    int lane = threadIdx.x & 31;
    int stride = gridDim.x * blockDim.x;
    int niter = (nR + stride - 1) / stride;
    for (int it = 0; it < niter; it++) {
        int i = it * stride + gtid;
        int c = (i < nR) ? g_cnt[i] : 0;
        int s = c;
        #pragma unroll
        for (int d = 1; d < 32; d <<= 1) {
            int t = __shfl_up_sync(0xffffffffu, s, d);
            if (lane >= d) s += t;
        }
        int warpTotal = __shfl_sync(0xffffffffu, s, 31);
        int base = 0;
        if (lane == 31) base = atomicAdd(&g_total, warpTotal);
        base = __shfl_sync(0xffffffffu, base, 31);
        int off = base + s - c;
        if (i < nR) { g_off[i] = off; g_cur[i] = off; }
    }
}

// ---------------- bin: place {li, f} and r into per-node segments ------------
__global__ __launch_bounds__(256) void bin_kernel(
    const int* __restrict__ idxL, const int* __restrict__ idxR,
    const float* __restrict__ ef, int nE)
{
    int i = blockIdx.x * blockDim.x + threadIdx.x;
    int stride = gridDim.x * blockDim.x;
    for (int e = i; e < nE; e += stride) {
        int r = idxR[e];
        int li = idxL[e];
        float f = ef[e];
        int pos = atomicAdd(&g_cur[r], 1);
        g_sorted[pos] = make_int2(li, __float_as_int(f));
        g_srtR[pos] = r;
    }
}

// ---------------- tiled projections (f32x2): 64x64 tile, 8x4 per thread ------
#define PROJ_PAD 68
__global__ __launch_bounds__(128) void proj_kernel(
    const float* __restrict__ XL, const float* __restrict__ WL, const float* __restrict__ bL,
    const float* __restrict__ XR, const float* __restrict__ WR,
    int nL, int nR, int nbL)
{
    bool isL = (int)blockIdx.x < nbL;
    const float* X = isL ? XL : XR;
    const float* W = isL ? WL : WR;
    float* Y = isL ? g_left_proj : g_right_proj;
    int n = isL ? nL : nR;
    int bid = isL ? blockIdx.x : blockIdx.x - nbL;
    int rowBase = bid * 64;

    __shared__ float WT[64 * PROJ_PAD];   // WT[k][j] = W[j][k]
    __shared__ float XS[64 * PROJ_PAD];
    __shared__ float bsh[EMB];
    for (int i = threadIdx.x; i < EMB * EMB; i += blockDim.x) {
        int j = i >> 6, k = i & 63;
        WT[k * PROJ_PAD + j] = W[i];
    }
    if (threadIdx.x < EMB) bsh[threadIdx.x] = isL ? bL[threadIdx.x] : 0.f;
    {
        const float4* X4 = (const float4*)X;
        #pragma unroll
        for (int it = 0; it < 8; it++) {
            int idx = it * 128 + threadIdx.x;
            int r = idx >> 4, k4 = idx & 15;
            int row = rowBase + r;
            float4 v = (row < n) ? X4[(size_t)row * 16 + k4]
                                 : make_float4(0.f, 0.f, 0.f, 0.f);
            *(float4*)(XS + r * PROJ_PAD + k4 * 4) = v;
        }
    }
    __syncthreads();

    int c16 = threadIdx.x & 15;
    int rg  = threadIdx.x >> 4;
    float4 b4 = ((const float4*)bsh)[c16];
    ull acc0[8], acc1[8];
    #pragma unroll
    for (int rr = 0; rr < 8; rr++) { acc0[rr] = pk2(b4.x, b4.y); acc1[rr] = pk2(b4.z, b4.w); }

    #pragma unroll 2
    for (int k4 = 0; k4 < 16; k4++) {
        ulonglong2 w2[4];
        #pragma unroll
        for (int kk = 0; kk < 4; kk++)
            w2[kk] = *(const ulonglong2*)(WT + (k4 * 4 + kk) * PROJ_PAD + c16 * 4);
        #pragma unroll
        for (int rr = 0; rr < 8; rr++) {
            float4 xf = *(const float4*)(XS + (rg * 8 + rr) * PROJ_PAD + k4 * 4);
            ull xp;
            xp = pk2(xf.x, xf.x); acc0[rr] = fma2(xp, w2[0].x, acc0[rr]); acc1[rr] = fma2(xp, w2[0].y, acc1[rr]);
            xp = pk2(xf.y, xf.y); acc0[rr] = fma2(xp, w2[1].x, acc0[rr]); acc1[rr] = fma2(xp, w2[1].y, acc1[rr]);
            xp = pk2(xf.z, xf.z); acc0[rr] = fma2(xp, w2[2].x, acc0[rr]); acc1[rr] = fma2(xp, w2[2].y, acc1[rr]);
            xp = pk2(xf.w, xf.w); acc0[rr] = fma2(xp, w2[3].x, acc0[rr]); acc1[rr] = fma2(xp, w2[3].y, acc1[rr]);
        }
    }

    float4* Y4 = (float4*)Y;
    #pragma unroll
    for (int rr = 0; rr < 8; rr++) {
        int row = rowBase + rg * 8 + rr;
        if (row < n) {
            float2 a = up2(acc0[rr]), b = up2(acc1[rr]);
            Y4[(size_t)row * 16 + c16] = make_float4(a.x, a.y, b.x, b.y);
        }
    }
}

// ---------------- BN1 stats: chunked over original edges ---------------------
__global__ __launch_bounds__(256) void stats_kernel(
    const int* __restrict__ idxL, const int* __restrict__ idxR,
    const float* __restrict__ ef, const float* __restrict__ Wedge, int nE)
{
    int lane = threadIdx.x & 31;
    int hl = lane & 15;
    unsigned hmask = (lane & 16) ? 0xFFFF0000u : 0x0000FFFFu;
    int grp = (blockIdx.x * blockDim.x + threadIdx.x) >> 4;
    int ngrp = (gridDim.x * blockDim.x) >> 4;
    float4 we = ((const float4*)Wedge)[hl];
    float4 s = make_float4(0.f, 0.f, 0.f, 0.f);
    float4 sq = make_float4(0.f, 0.f, 0.f, 0.f);
    const float4* LP = (const float4*)g_left_proj;
    const float4* RP = (const float4*)g_right_proj;

    int nfull = nE >> 4;
    for (int ch = grp; ch < nfull; ch += ngrp) {
        int e = (ch << 4) + hl;
        int li = idxL[e], ri = idxR[e];
        float f = ef[e];
        #pragma unroll
        for (int j = 0; j < 16; j++) {
            int lj   = __shfl_sync(hmask, li, j, 16);
            int rj   = __shfl_sync(hmask, ri, j, 16);
            float fj = __shfl_sync(hmask, f, j, 16);
            float4 lp = LP[(size_t)lj * 16 + hl];
            float4 rp = RP[(size_t)rj * 16 + hl];
            float x;
            x = fmaf(fj, we.x, lp.x + rp.x); s.x += x; sq.x = fmaf(x, x, sq.x);
            x = fmaf(fj, we.y, lp.y + rp.y); s.y += x; sq.y = fmaf(x, x, sq.y);
            x = fmaf(fj, we.z, lp.z + rp.z); s.z += x; sq.z = fmaf(x, x, sq.z);
            x = fmaf(fj, we.w, lp.w + rp.w); s.w += x; sq.w = fmaf(x, x, sq.w);
        }
    }
    if (grp == 0) {
        for (int e = nfull << 4; e < nE; e++) {
            int lj = idxL[e], rj = idxR[e];
            float fj = ef[e];
            float4 lp = LP[(size_t)lj * 16 + hl];
            float4 rp = RP[(size_t)rj * 16 + hl];
            float x;
            x = fmaf(fj, we.x, lp.x + rp.x); s.x += x; sq.x = fmaf(x, x, sq.x);
            x = fmaf(fj, we.y, lp.y + rp.y); s.y += x; sq.y = fmaf(x, x, sq.y);
            x = fmaf(fj, we.z, lp.z + rp.z); s.z += x; sq.z = fmaf(x, x, sq.z);
            x = fmaf(fj, we.w, lp.w + rp.w); s.w += x; sq.w = fmaf(x, x, sq.w);
        }
    }
    s.x += __shfl_xor_sync(0xffffffffu, s.x, 16);
    s.y += __shfl_xor_sync(0xffffffffu, s.y, 16);
    s.z += __shfl_xor_sync(0xffffffffu, s.z, 16);
    s.w += __shfl_xor_sync(0xffffffffu, s.w, 16);
    sq.x += __shfl_xor_sync(0xffffffffu, sq.x, 16);
    sq.y += __shfl_xor_sync(0xffffffffu, sq.y, 16);
    sq.z += __shfl_xor_sync(0xffffffffu, sq.z, 16);
    sq.w += __shfl_xor_sync(0xffffffffu, sq.w, 16);

    __shared__ float cs[EMB], cq[EMB];
    if (threadIdx.x < EMB) { cs[threadIdx.x] = 0.f; cq[threadIdx.x] = 0.f; }
    __syncthreads();
    if (lane < 16) {
        atomicAdd(&cs[4 * hl + 0], s.x);
        atomicAdd(&cs[4 * hl + 1], s.y);
        atomicAdd(&cs[4 * hl + 2], s.z);
        atomicAdd(&cs[4 * hl + 3], s.w);
        atomicAdd(&cq[4 * hl + 0], sq.x);
        atomicAdd(&cq[4 * hl + 1], sq.y);
        atomicAdd(&cq[4 * hl + 2], sq.z);
        atomicAdd(&cq[4 * hl + 3], sq.w);
    }
    __syncthreads();
    if (threadIdx.x < EMB) {
        atomicAdd(&g_sum1[threadIdx.x], cs[threadIdx.x]);
        atomicAdd(&g_sumsq1[threadIdx.x], cq[threadIdx.x]);
    }
}

// ---------------- BN finalize ------------------------------------------------
__global__ void bn_fin_kernel(const float* __restrict__ sum, const float* __restrict__ sumsq,
                              const float* __restrict__ gamma, const float* __restrict__ beta,
                              float* __restrict__ scale, float* __restrict__ shift, float invN)
{
    int c = threadIdx.x;
    if (c < EMB) {
        float m = sum[c] * invN;
        float v = sumsq[c] * invN - m * m;
        float sc = gamma[c] * rsqrtf(v + BN_EPS);
        scale[c] = sc;
        shift[c] = beta[c] - m * sc;
    }
}

// ---------------- seg v4: stats-shaped, branch-free run-length ---------------
// Unconditional lp+rp gathers (full MLP); run boundaries handled with a
// select-based accumulator reset and a predicated float4 atomic flush.
__global__ __launch_bounds__(256) void seg_kernel(const float* __restrict__ Wedge, int nE)
{
    int lane = threadIdx.x & 31;
    int hl = lane & 15;
    unsigned hmask = (lane & 16) ? 0xFFFF0000u : 0x0000FFFFu;
    int grp = (blockIdx.x * blockDim.x + threadIdx.x) >> 4;
    int ngrp = (gridDim.x * blockDim.x) >> 4;
    float4 we = ((const float4*)Wedge)[hl];
    float4 sc = ((const float4*)g_scale1)[hl];
    float4 sh = ((const float4*)g_shift1)[hl];
    const float4* LP = (const float4*)g_left_proj;
    const float4* RP = (const float4*)g_right_proj;
    float4* Sv = (float4*)g_S;

    int nfull = nE >> 4;
    for (int ch = grp; ch < nfull; ch += ngrp) {
        int e = (ch << 4) + hl;
        int2 a = g_sorted[e];
        int r = g_srtR[e];
        int li = a.x;
        float f = __int_as_float(a.y);
        float4 acc = make_float4(0.f, 0.f, 0.f, 0.f);
        int rprev = -1;
        #pragma unroll
        for (int j = 0; j < 16; j++) {
            int rj   = __shfl_sync(hmask, r, j, 16);
            int lj   = __shfl_sync(hmask, li, j, 16);
            float fj = __shfl_sync(hmask, f, j, 16);
            float4 lp = LP[(size_t)lj * 16 + hl];     // unconditional gathers
            float4 rp = RP[(size_t)rj * 16 + hl];     // -> full load batching
            float4 y;
            float x;
            x = fmaf(fj, we.x, lp.x + rp.x); y.x = fmaxf(fmaf(x, sc.x, sh.x), 0.f);
            x = fmaf(fj, we.y, lp.y + rp.y); y.y = fmaxf(fmaf(x, sc.y, sh.y), 0.f);
            x = fmaf(fj, we.z, lp.z + rp.z); y.z = fmaxf(fmaf(x, sc.z, sh.z), 0.f);
            x = fmaf(fj, we.w, lp.w + rp.w); y.w = fmaxf(fmaf(x, sc.w, sh.w), 0.f);
            bool nw = (rj != rprev);
            if (nw && rprev >= 0)                     // predicated flush
                atomicAdd(&Sv[(size_t)rprev * 16 + hl], acc);
            float m = nw ? 0.f : 1.f;                 // branch-free reset
            acc.x = fmaf(acc.x, m, y.x);
            acc.y = fmaf(acc.y, m, y.y);
            acc.z = fmaf(acc.z, m, y.z);
            acc.w = fmaf(acc.w, m, y.w);
            rprev = rj;
        }
        atomicAdd(&Sv[(size_t)rprev * 16 + hl], acc); // chunk-final flush
    }
    if (grp == 0) {
        for (int e = nfull << 4; e < nE; e++) {
            int2 a = g_sorted[e];
            int rj = g_srtR[e];
            float4 lp = LP[(size_t)a.x * 16 + hl];
            float4 rp = RP[(size_t)rj * 16 + hl];
            float fj = __int_as_float(a.y);
            float4 y;
            float x;
            x = fmaf(fj, we.x, lp.x + rp.x); y.x = fmaxf(fmaf(x, sc.x, sh.x), 0.f);
            x = fmaf(fj, we.y, lp.y + rp.y); y.y = fmaxf(fmaf(x, sc.y, sh.y), 0.f);
            x = fmaf(fj, we.z, lp.z + rp.z); y.z = fmaxf(fmaf(x, sc.z, sh.z), 0.f);
            x = fmaf(fj, we.w, lp.w + rp.w); y.w = fmaxf(fmaf(x, sc.w, sh.w), 0.f);
            atomicAdd(&Sv[(size_t)rj * 16 + hl], y);
        }
    }
}

// ---------------- conv = S @ Wf^T + cnt*b (f32x2), fused BN2 stats -----------
__global__ __launch_bounds__(128) void conv_stats_kernel(
    const float* __restrict__ X, const float* __restrict__ W,
    const float* __restrict__ bias, float* __restrict__ Y, int n)
{
    __shared__ float WT[EMB * EMB];
    __shared__ float bsh[EMB];
    __shared__ float cs[EMB], cq[EMB];
    for (int i = threadIdx.x; i < EMB * EMB; i += blockDim.x) {
        int j = i >> 6, k = i & 63;
        WT[k * EMB + j] = W[i];
    }
    if (threadIdx.x < EMB) {
        bsh[threadIdx.x] = bias[threadIdx.x];
        cs[threadIdx.x] = 0.f;
        cq[threadIdx.x] = 0.f;
    }
    __syncthreads();

    int row = blockIdx.x * blockDim.x + threadIdx.x;
    int lane = threadIdx.x & 31;
    bool valid = row < n;
    float acc[EMB];
    if (valid) {
        float bs = (float)g_cnt[row];
        ull acc2[32];
        #pragma unroll
        for (int p = 0; p < 32; p++)
            acc2[p] = pk2(bsh[2 * p] * bs, bsh[2 * p + 1] * bs);
        const float4* Xr = (const float4*)(X + (size_t)row * EMB);
        #pragma unroll 2
        for (int k4 = 0; k4 < 16; k4++) {
            float4 xv = Xr[k4];
            float xs4[4] = {xv.x, xv.y, xv.z, xv.w};
            #pragma unroll
            for (int kk = 0; kk < 4; kk++) {
                ull xp = pk2(xs4[kk], xs4[kk]);
                const ulonglong2* wq = (const ulonglong2*)(WT + (k4 * 4 + kk) * EMB);
                #pragma unroll
                for (int p = 0; p < 16; p++) {
                    ulonglong2 w2 = wq[p];
                    acc2[2 * p]     = fma2(xp, w2.x, acc2[2 * p]);
                    acc2[2 * p + 1] = fma2(xp, w2.y, acc2[2 * p + 1]);
                }
            }
        }
        #pragma unroll
        for (int p = 0; p < 32; p++) {
            float2 f = up2(acc2[p]);
            acc[2 * p] = f.x;
            acc[2 * p + 1] = f.y;
        }
        float4* Yr = (float4*)(Y + (size_t)row * EMB);
        #pragma unroll
        for (int q = 0; q < EMB / 4; q++)
            Yr[q] = make_float4(acc[4 * q], acc[4 * q + 1], acc[4 * q + 2], acc[4 * q + 3]);
    } else {
        #pragma unroll
        for (int j = 0; j < EMB; j++) acc[j] = 0.f;
    }
    #pragma unroll
    for (int j = 0; j < EMB; j++) {
        float v = acc[j];
        float v2 = v * v;
        #pragma unroll
        for (int o = 16; o; o >>= 1) {
            v  += __shfl_xor_sync(0xffffffffu, v, o);
            v2 += __shfl_xor_sync(0xffffffffu, v2, o);
        }
        if (lane == 0) { atomicAdd(&cs[j], v); atomicAdd(&cq[j], v2); }
    }
    __syncthreads();
    if (threadIdx.x < EMB) {
        atomicAdd(&g_sum2[threadIdx.x], cs[threadIdx.x]);
        atomicAdd(&g_sumsq2[threadIdx.x], cq[threadIdx.x]);
    }
}

// ---------------- final: bn2 + concat + 2-layer MLP (f32x2) ------------------
__global__ __launch_bounds__(128) void final_kernel(
    const float* __restrict__ right,
    const float* __restrict__ W1, const float* __restrict__ b1,
    const float* __restrict__ W2, const float* __restrict__ b2,
    float* __restrict__ out, int nR)
{
    __shared__ float Wsh[2 * EMB * EMB];
    __shared__ float sb[EMB], ssc[EMB], ssh[EMB];
    for (int i = threadIdx.x; i < 2 * EMB * EMB; i += blockDim.x) {
        int j = i >> 7, c = i & 127;       // W1 is [64,128]
        Wsh[c * EMB + j] = W1[i];
    }
    if (threadIdx.x < EMB) {
        sb[threadIdx.x] = b1[threadIdx.x];
        ssc[threadIdx.x] = g_scale2[threadIdx.x];
        ssh[threadIdx.x] = g_shift2[threadIdx.x];
    }
    __syncthreads();

    int row = blockIdx.x * blockDim.x + threadIdx.x;
    float h[EMB];
    if (row < nR) {
        ull h2[32];
        #pragma unroll
        for (int p = 0; p < 32; p++) h2[p] = pk2(sb[2 * p], sb[2 * p + 1]);
        const float4* cv = (const float4*)(g_conv + (size_t)row * EMB);
        #pragma unroll 2
        for (int k4 = 0; k4 < 16; k4++) {
            float4 v = cv[k4];
            int c = k4 * 4;
            float xs4[4] = {
                fmaf(v.x, ssc[c], ssh[c]),
                fmaf(v.y, ssc[c + 1], ssh[c + 1]),
                fmaf(v.z, ssc[c + 2], ssh[c + 2]),
                fmaf(v.w, ssc[c + 3], ssh[c + 3]) };
            #pragma unroll
            for (int kk = 0; kk < 4; kk++) {
                ull xp = pk2(xs4[kk], xs4[kk]);
                const ulonglong2* wq = (const ulonglong2*)(Wsh + (c + kk) * EMB);
                #pragma unroll
                for (int p = 0; p < 16; p++) {
                    ulonglong2 w2 = wq[p];
                    h2[2 * p]     = fma2(xp, w2.x, h2[2 * p]);
                    h2[2 * p + 1] = fma2(xp, w2.y, h2[2 * p + 1]);
                }
            }
        }
        const float4* rf = (const float4*)(right + (size_t)row * EMB);
        #pragma unroll 2
        for (int k4 = 0; k4 < 16; k4++) {
            float4 v = rf[k4];
            int c = 64 + k4 * 4;
            float xs4[4] = {v.x, v.y, v.z, v.w};
            #pragma unroll
            for (int kk = 0; kk < 4; kk++) {
                ull xp = pk2(xs4[kk], xs4[kk]);
                const ulonglong2* wq = (const ulonglong2*)(Wsh + (c + kk) * EMB);
                #pragma unroll
                for (int p = 0; p < 16; p++) {
                    ulonglong2 w2 = wq[p];
                    h2[2 * p]     = fma2(xp, w2.x, h2[2 * p]);
                    h2[2 * p + 1] = fma2(xp, w2.y, h2[2 * p + 1]);
                }
            }
        }
        #pragma unroll
        for (int p = 0; p < 32; p++) {
            float2 f = up2(h2[p]);
            h[2 * p] = fmaxf(f.x, 0.f);
            h[2 * p + 1] = fmaxf(f.y, 0.f);
        }
    }
    __syncthreads();
    for (int i = threadIdx.x; i < EMB * EMB; i += blockDim.x) {
        int j = i >> 6, c = i & 63;
        Wsh[c * EMB + j] = W2[i];
    }
    if (threadIdx.x < EMB) sb[threadIdx.x] = b2[threadIdx.x];
    __syncthreads();
    if (row < nR) {
        float* orow = out + (size_t)row * EMB;
        #pragma unroll
        for (int jb = 0; jb < 4; jb++) {
            ull a2[8];
            #pragma unroll
            for (int q = 0; q < 8; q++)
                a2[q] = pk2(sb[jb * 16 + 2 * q], sb[jb * 16 + 2 * q + 1]);
            #pragma unroll 4
            for (int c = 0; c < EMB; c++) {
                ull xp = pk2(h[c], h[c]);
                const ulonglong2* wq = (const ulonglong2*)(Wsh + c * EMB + jb * 16);
                #pragma unroll
                for (int q = 0; q < 4; q++) {
                    ulonglong2 w2 = wq[q];
                    a2[2 * q]     = fma2(xp, w2.x, a2[2 * q]);
                    a2[2 * q + 1] = fma2(xp, w2.y, a2[2 * q + 1]);
                }
            }
            float4* o4 = (float4*)(orow + jb * 16);
            #pragma unroll
            for (int q = 0; q < 4; q++) {
                float2 f0 = up2(a2[2 * q]), f1 = up2(a2[2 * q + 1]);
                o4[q] = make_float4(fmaxf(f0.x, 0.f), fmaxf(f0.y, 0.f),
                                    fmaxf(f1.x, 0.f), fmaxf(f1.y, 0.f));
            }
        }
    }
}

// ---------------- launch -----------------------------------------------------
extern "C" void kernel_launch(void* const* d_in, const int* in_sizes, int n_in,
                              void* d_out, int out_size)
{
    const float* left  = (const float*)d_in[0];
    const int*   eidx  = (const int*)d_in[1];
    const float* ef    = (const float*)d_in[2];
    const float* right = (const float*)d_in[3];
    int off = (n_in >= 19) ? 1 : 0;
    const float* W_left    = (const float*)d_in[4 + off];
    const float* b_left    = (const float*)d_in[5 + off];
    const float* W_edge    = (const float*)d_in[6 + off];
    const float* W_right   = (const float*)d_in[7 + off];
    const float* bn1_gamma = (const float*)d_in[8 + off];
    const float* bn1_beta  = (const float*)d_in[9 + off];
    const float* W_final   = (const float*)d_in[10 + off];
    const float* b_final   = (const float*)d_in[11 + off];
    const float* bn2_gamma = (const float*)d_in[12 + off];
    const float* bn2_beta  = (const float*)d_in[13 + off];
    const float* W_out1    = (const float*)d_in[14 + off];
    const float* b_out1    = (const float*)d_in[15 + off];
    const float* W_out2    = (const float*)d_in[16 + off];
    const float* b_out2    = (const float*)d_in[17 + off];
    float* out = (float*)d_out;

    int nL = in_sizes[0] / EMB;
    int nE = in_sizes[2];
    int nR = in_sizes[3] / EMB;

    float* Sp; cudaGetSymbolAddress((void**)&Sp, g_S);
    float* cp; cudaGetSymbolAddress((void**)&cp, g_conv);
    float* s1; cudaGetSymbolAddress((void**)&s1, g_sum1);
    float* q1; cudaGetSymbolAddress((void**)&q1, g_sumsq1);
    float* sc1; cudaGetSymbolAddress((void**)&sc1, g_scale1);
    float* sh1; cudaGetSymbolAddress((void**)&sh1, g_shift1);
    float* s2; cudaGetSymbolAddress((void**)&s2, g_sum2);
    float* q2; cudaGetSymbolAddress((void**)&q2, g_sumsq2);
    float* sc2; cudaGetSymbolAddress((void**)&sc2, g_scale2);
    float* sh2; cudaGetSymbolAddress((void**)&sh2, g_shift2);

    int nbL = (nL + 63) / 64;
    int nbR = (nR + 63) / 64;
    int nbRrow = (nR + 127) / 128;

    // idx 0) zero counters/stats/S
    zero_kernel<<<1024, 256>>>(nR, nR * EMB);
    // idx 1) degree histogram
    count_kernel<<<1184, 256>>>(eidx + nE, nE);
    // idx 2) contiguous segment offsets
    assign_kernel<<<(nR + 255) / 256, 256>>>(nR);
    // idx 3) tiled projections (f32x2)             <- profiled launch (index 3)
    proj_kernel<<<nbL + nbR, 128>>>(left, W_left, b_left, right, W_right, nL, nR, nbL);
    // idx 4) bin {left_idx, f, r} into segments
    bin_kernel<<<1184, 256>>>(eidx, eidx + nE, ef, nE);
    // idx 5) BN1 stats (chunked, original order)
    stats_kernel<<<1184, 256>>>(eidx, eidx + nE, ef, W_edge, nE);
    // idx 6) BN1 finalize
    bn_fin_kernel<<<1, EMB>>>(s1, q1, bn1_gamma, bn1_beta, sc1, sh1, 1.0f / (float)nE);
    // idx 7) segment sum v4: stats-shaped, branch-free run-length
    seg_kernel<<<1184, 256>>>(W_edge, nE);
    // idx 8) conv GEMM (f32x2) + fused BN2 stats
    conv_stats_kernel<<<nbRrow, 128>>>(Sp, W_final, b_final, cp, nR);
    // idx 9) BN2 finalize
    bn_fin_kernel<<<1, EMB>>>(s2, q2, bn2_gamma, bn2_beta, sc2, sh2, 1.0f / (float)nR);
    // idx 10) final MLP (f32x2)
    final_kernel<<<nbRrow, 128>>>(right, W_out1, b_out1, W_out2, b_out2, out, nR);
}

// round 11
// speedup vs baseline: 1.4522x; 1.2376x over previous
#include <cuda_runtime.h>
#include <cuda_bf16.h>

#define EMB 64
#define BN_EPS 1e-5f
#define MAX_L 50000
#define MAX_R 100000
#define MAX_E 1100000

typedef unsigned long long ull;

// ---------------- f32x2 packed-FMA helpers (FFMA2) ---------------------------
__device__ __forceinline__ ull pk2(float lo, float hi) {
    ull r; asm("mov.b64 %0, {%1, %2};" : "=l"(r) : "f"(lo), "f"(hi)); return r;
}
__device__ __forceinline__ float2 up2(ull v) {
    float2 f; asm("mov.b64 {%0, %1}, %2;" : "=f"(f.x), "=f"(f.y) : "l"(v)); return f;
}
__device__ __forceinline__ ull fma2(ull a, ull b, ull c) {
    ull d; asm("fma.rn.f32x2 %0, %1, %2, %3;" : "=l"(d) : "l"(a), "l"(b), "l"(c)); return d;
}

// ---------------- scratch (static device globals; no allocation) -------------
__device__ float g_left_proj[MAX_L * EMB];
__device__ float g_right_proj[MAX_R * EMB];
__device__ float g_S[MAX_R * EMB];
__device__ float g_conv[MAX_R * EMB];
__device__ int   g_cnt[MAX_R];
__device__ int   g_off[MAX_R];
__device__ int   g_cur[MAX_R];
__device__ int   g_total;
__device__ int2  g_sorted[MAX_E];
__device__ float g_sum1[EMB], g_sumsq1[EMB], g_scale1[EMB], g_shift1[EMB];
__device__ float g_sum2[EMB], g_sumsq2[EMB], g_scale2[EMB], g_shift2[EMB];

// ---------------- zero scratch (no g_S zeroing needed anymore) ---------------
__global__ void zero_kernel(int nR) {
    int i = blockIdx.x * blockDim.x + threadIdx.x;
    int stride = gridDim.x * blockDim.x;
    for (int k = i; k < nR; k += stride) g_cnt[k] = 0;
    if (i < EMB) { g_sum1[i] = 0.f; g_sumsq1[i] = 0.f; g_sum2[i] = 0.f; g_sumsq2[i] = 0.f; }
    if (i == 0) g_total = 0;
}

// ---------------- count: histogram of right indices --------------------------
__global__ __launch_bounds__(256) void count_kernel(const int* __restrict__ idxR, int nE) {
    int i = blockIdx.x * blockDim.x + threadIdx.x;
    int stride = gridDim.x * blockDim.x;
    for (int e = i; e < nE; e += stride) atomicAdd(&g_cnt[idxR[e]], 1);
}

// ---------------- assign: contiguous segment offsets (order-free) ------------
__global__ __launch_bounds__(256) void assign_kernel(int nR) {
    int gtid = blockIdx.x * blockDim.x + threadIdx.x;
    int lane = threadIdx.x & 31;
    int stride = gridDim.x * blockDim.x;
    int niter = (nR + stride - 1) / stride;
    for (int it = 0; it < niter; it++) {
        int i = it * stride + gtid;
        int c = (i < nR) ? g_cnt[i] : 0;
        int s = c;
        #pragma unroll
        for (int d = 1; d < 32; d <<= 1) {
            int t = __shfl_up_sync(0xffffffffu, s, d);
            if (lane >= d) s += t;
        }
        int warpTotal = __shfl_sync(0xffffffffu, s, 31);
        int base = 0;
        if (lane == 31) base = atomicAdd(&g_total, warpTotal);
        base = __shfl_sync(0xffffffffu, base, 31);
        int off = base + s - c;
        if (i < nR) { g_off[i] = off; g_cur[i] = off; }
    }
}

// ---------------- bin: place {li, f} into per-node segments ------------------
__global__ __launch_bounds__(256) void bin_kernel(
    const int* __restrict__ idxL, const int* __restrict__ idxR,
    const float* __restrict__ ef, int nE)
{
    int i = blockIdx.x * blockDim.x + threadIdx.x;
    int stride = gridDim.x * blockDim.x;
    for (int e = i; e < nE; e += stride) {
        int r = idxR[e];
        int li = idxL[e];
        float f = ef[e];
        int pos = atomicAdd(&g_cur[r], 1);
        g_sorted[pos] = make_int2(li, __float_as_int(f));
    }
}

// ---------------- tiled projections (f32x2): 64x64 tile, 8x4 per thread ------
#define PROJ_PAD 68
__global__ __launch_bounds__(128) void proj_kernel(
    const float* __restrict__ XL, const float* __restrict__ WL, const float* __restrict__ bL,
    const float* __restrict__ XR, const float* __restrict__ WR,
    int nL, int nR, int nbL)
{
    bool isL = (int)blockIdx.x < nbL;
    const float* X = isL ? XL : XR;
    const float* W = isL ? WL : WR;
    float* Y = isL ? g_left_proj : g_right_proj;
    int n = isL ? nL : nR;
    int bid = isL ? blockIdx.x : blockIdx.x - nbL;
    int rowBase = bid * 64;

    __shared__ float WT[64 * PROJ_PAD];   // WT[k][j] = W[j][k]
    __shared__ float XS[64 * PROJ_PAD];
    __shared__ float bsh[EMB];
    for (int i = threadIdx.x; i < EMB * EMB; i += blockDim.x) {
        int j = i >> 6, k = i & 63;
        WT[k * PROJ_PAD + j] = W[i];
    }
    if (threadIdx.x < EMB) bsh[threadIdx.x] = isL ? bL[threadIdx.x] : 0.f;
    {
        const float4* X4 = (const float4*)X;
        #pragma unroll
        for (int it = 0; it < 8; it++) {
            int idx = it * 128 + threadIdx.x;
            int r = idx >> 4, k4 = idx & 15;
            int row = rowBase + r;
            float4 v = (row < n) ? X4[(size_t)row * 16 + k4]
                                 : make_float4(0.f, 0.f, 0.f, 0.f);
            *(float4*)(XS + r * PROJ_PAD + k4 * 4) = v;
        }
    }
    __syncthreads();

    int c16 = threadIdx.x & 15;
    int rg  = threadIdx.x >> 4;
    float4 b4 = ((const float4*)bsh)[c16];
    ull acc0[8], acc1[8];
    #pragma unroll
    for (int rr = 0; rr < 8; rr++) { acc0[rr] = pk2(b4.x, b4.y); acc1[rr] = pk2(b4.z, b4.w); }

    #pragma unroll 2
    for (int k4 = 0; k4 < 16; k4++) {
        ulonglong2 w2[4];
        #pragma unroll
        for (int kk = 0; kk < 4; kk++)
            w2[kk] = *(const ulonglong2*)(WT + (k4 * 4 + kk) * PROJ_PAD + c16 * 4);
        #pragma unroll
        for (int rr = 0; rr < 8; rr++) {
            float4 xf = *(const float4*)(XS + (rg * 8 + rr) * PROJ_PAD + k4 * 4);
            ull xp;
            xp = pk2(xf.x, xf.x); acc0[rr] = fma2(xp, w2[0].x, acc0[rr]); acc1[rr] = fma2(xp, w2[0].y, acc1[rr]);
            xp = pk2(xf.y, xf.y); acc0[rr] = fma2(xp, w2[1].x, acc0[rr]); acc1[rr] = fma2(xp, w2[1].y, acc1[rr]);
            xp = pk2(xf.z, xf.z); acc0[rr] = fma2(xp, w2[2].x, acc0[rr]); acc1[rr] = fma2(xp, w2[2].y, acc1[rr]);
            xp = pk2(xf.w, xf.w); acc0[rr] = fma2(xp, w2[3].x, acc0[rr]); acc1[rr] = fma2(xp, w2[3].y, acc1[rr]);
        }
    }

    float4* Y4 = (float4*)Y;
    #pragma unroll
    for (int rr = 0; rr < 8; rr++) {
        int row = rowBase + rg * 8 + rr;
        if (row < n) {
            float2 a = up2(acc0[rr]), b = up2(acc1[rr]);
            Y4[(size_t)row * 16 + c16] = make_float4(a.x, a.y, b.x, b.y);
        }
    }
}

// ---------------- BN1 stats: chunked over original edges ---------------------
__global__ __launch_bounds__(256) void stats_kernel(
    const int* __restrict__ idxL, const int* __restrict__ idxR,
    const float* __restrict__ ef, const float* __restrict__ Wedge, int nE)
{
    int lane = threadIdx.x & 31;
    int hl = lane & 15;
    unsigned hmask = (lane & 16) ? 0xFFFF0000u : 0x0000FFFFu;
    int grp = (blockIdx.x * blockDim.x + threadIdx.x) >> 4;
    int ngrp = (gridDim.x * blockDim.x) >> 4;
    float4 we = ((const float4*)Wedge)[hl];
    float4 s = make_float4(0.f, 0.f, 0.f, 0.f);
    float4 sq = make_float4(0.f, 0.f, 0.f, 0.f);
    const float4* LP = (const float4*)g_left_proj;
    const float4* RP = (const float4*)g_right_proj;

    int nfull = nE >> 4;
    for (int ch = grp; ch < nfull; ch += ngrp) {
        int e = (ch << 4) + hl;
        int li = idxL[e], ri = idxR[e];
        float f = ef[e];
        #pragma unroll
        for (int j = 0; j < 16; j++) {
            int lj   = __shfl_sync(hmask, li, j, 16);
            int rj   = __shfl_sync(hmask, ri, j, 16);
            float fj = __shfl_sync(hmask, f, j, 16);
            float4 lp = LP[(size_t)lj * 16 + hl];
            float4 rp = RP[(size_t)rj * 16 + hl];
            float x;
            x = fmaf(fj, we.x, lp.x + rp.x); s.x += x; sq.x = fmaf(x, x, sq.x);
            x = fmaf(fj, we.y, lp.y + rp.y); s.y += x; sq.y = fmaf(x, x, sq.y);
            x = fmaf(fj, we.z, lp.z + rp.z); s.z += x; sq.z = fmaf(x, x, sq.z);
            x = fmaf(fj, we.w, lp.w + rp.w); s.w += x; sq.w = fmaf(x, x, sq.w);
        }
    }
    if (grp == 0) {
        for (int e = nfull << 4; e < nE; e++) {
            int lj = idxL[e], rj = idxR[e];
            float fj = ef[e];
            float4 lp = LP[(size_t)lj * 16 + hl];
            float4 rp = RP[(size_t)rj * 16 + hl];
            float x;
            x = fmaf(fj, we.x, lp.x + rp.x); s.x += x; sq.x = fmaf(x, x, sq.x);
            x = fmaf(fj, we.y, lp.y + rp.y); s.y += x; sq.y = fmaf(x, x, sq.y);
            x = fmaf(fj, we.z, lp.z + rp.z); s.z += x; sq.z = fmaf(x, x, sq.z);
            x = fmaf(fj, we.w, lp.w + rp.w); s.w += x; sq.w = fmaf(x, x, sq.w);
        }
    }
    s.x += __shfl_xor_sync(0xffffffffu, s.x, 16);
    s.y += __shfl_xor_sync(0xffffffffu, s.y, 16);
    s.z += __shfl_xor_sync(0xffffffffu, s.z, 16);
    s.w += __shfl_xor_sync(0xffffffffu, s.w, 16);
    sq.x += __shfl_xor_sync(0xffffffffu, sq.x, 16);
    sq.y += __shfl_xor_sync(0xffffffffu, sq.y, 16);
    sq.z += __shfl_xor_sync(0xffffffffu, sq.z, 16);
    sq.w += __shfl_xor_sync(0xffffffffu, sq.w, 16);

    __shared__ float cs[EMB], cq[EMB];
    if (threadIdx.x < EMB) { cs[threadIdx.x] = 0.f; cq[threadIdx.x] = 0.f; }
    __syncthreads();
    if (lane < 16) {
        atomicAdd(&cs[4 * hl + 0], s.x);
        atomicAdd(&cs[4 * hl + 1], s.y);
        atomicAdd(&cs[4 * hl + 2], s.z);
        atomicAdd(&cs[4 * hl + 3], s.w);
        atomicAdd(&cq[4 * hl + 0], sq.x);
        atomicAdd(&cq[4 * hl + 1], sq.y);
        atomicAdd(&cq[4 * hl + 2], sq.z);
        atomicAdd(&cq[4 * hl + 3], sq.w);
    }
    __syncthreads();
    if (threadIdx.x < EMB) {
        atomicAdd(&g_sum1[threadIdx.x], cs[threadIdx.x]);
        atomicAdd(&g_sumsq1[threadIdx.x], cq[threadIdx.x]);
    }
}

// ---------------- BN finalize ------------------------------------------------
__global__ void bn_fin_kernel(const float* __restrict__ sum, const float* __restrict__ sumsq,
                              const float* __restrict__ gamma, const float* __restrict__ beta,
                              float* __restrict__ scale, float* __restrict__ shift, float invN)
{
    int c = threadIdx.x;
    if (c < EMB) {
        float m = sum[c] * invN;
        float v = sumsq[c] * invN - m * m;
        float sc = gamma[c] * rsqrtf(v + BN_EPS);
        scale[c] = sc;
        shift[c] = beta[c] - m * sc;
    }
}

// ---------------- seg v5: per-node, batched gathers, ZERO atomics ------------
// One 16-lane group per right node. Edge descriptors loaded cooperatively
// (coalesced), then batches of 8 unconditional gathers (dummy idx 0, masked
// accumulate) with NO writes inside the batch -> loads batch like stats.
__global__ __launch_bounds__(256) void seg_kernel(const float* __restrict__ Wedge, int nR)
{
    int lane = threadIdx.x & 31;
    int hl = lane & 15;
    unsigned hmask = (lane & 16) ? 0xFFFF0000u : 0x0000FFFFu;
    int grp = (blockIdx.x * blockDim.x + threadIdx.x) >> 4;
    int ngrp = (gridDim.x * blockDim.x) >> 4;
    float4 we = ((const float4*)Wedge)[hl];
    float4 sc = ((const float4*)g_scale1)[hl];
    float4 sh = ((const float4*)g_shift1)[hl];
    const float4* LP = (const float4*)g_left_proj;
    const float4* RP = (const float4*)g_right_proj;
    float4* Sv = (float4*)g_S;

    for (int r = grp; r < nR; r += ngrp) {
        int cnt = g_cnt[r];
        int off = g_off[r];
        float4 rp = RP[(size_t)r * 16 + hl];
        float4 acc = make_float4(0.f, 0.f, 0.f, 0.f);
        for (int k = 0; k < cnt; k += 8) {
            int rem = cnt - k;
            int2 d = make_int2(0, 0);
            if (hl < 8 && hl < rem) d = g_sorted[off + k + hl];
            #pragma unroll
            for (int j = 0; j < 8; j++) {
                int lj = __shfl_sync(hmask, d.x, j, 16);
                int fb = __shfl_sync(hmask, d.y, j, 16);
                float4 lp = LP[(size_t)lj * 16 + hl];   // unconditional gather
                float fj = __int_as_float(fb);
                float m = (j < rem) ? 1.f : 0.f;
                float x, y;
                x = fmaf(fj, we.x, lp.x + rp.x); y = fmaxf(fmaf(x, sc.x, sh.x), 0.f); acc.x = fmaf(y, m, acc.x);
                x = fmaf(fj, we.y, lp.y + rp.y); y = fmaxf(fmaf(x, sc.y, sh.y), 0.f); acc.y = fmaf(y, m, acc.y);
                x = fmaf(fj, we.z, lp.z + rp.z); y = fmaxf(fmaf(x, sc.z, sh.z), 0.f); acc.z = fmaf(y, m, acc.z);
                x = fmaf(fj, we.w, lp.w + rp.w); y = fmaxf(fmaf(x, sc.w, sh.w), 0.f); acc.w = fmaf(y, m, acc.w);
            }
        }
        Sv[(size_t)r * 16 + hl] = acc;    // single write, no atomics
    }
}

// ---------------- conv = S @ Wf^T + cnt*b (f32x2), fused BN2 stats -----------
__global__ __launch_bounds__(128) void conv_stats_kernel(
    const float* __restrict__ X, const float* __restrict__ W,
    const float* __restrict__ bias, float* __restrict__ Y, int n)
{
    __shared__ float WT[EMB * EMB];
    __shared__ float bsh[EMB];
    __shared__ float cs[EMB], cq[EMB];
    for (int i = threadIdx.x; i < EMB * EMB; i += blockDim.x) {
        int j = i >> 6, k = i & 63;
        WT[k * EMB + j] = W[i];
    }
    if (threadIdx.x < EMB) {
        bsh[threadIdx.x] = bias[threadIdx.x];
        cs[threadIdx.x] = 0.f;
        cq[threadIdx.x] = 0.f;
    }
    __syncthreads();

    int row = blockIdx.x * blockDim.x + threadIdx.x;
    int lane = threadIdx.x & 31;
    bool valid = row < n;
    float acc[EMB];
    if (valid) {
        float bs = (float)g_cnt[row];
        ull acc2[32];
        #pragma unroll
        for (int p = 0; p < 32; p++)
            acc2[p] = pk2(bsh[2 * p] * bs, bsh[2 * p + 1] * bs);
        const float4* Xr = (const float4*)(X + (size_t)row * EMB);
        #pragma unroll 2
        for (int k4 = 0; k4 < 16; k4++) {
            float4 xv = Xr[k4];
            float xs4[4] = {xv.x, xv.y, xv.z, xv.w};
            #pragma unroll
            for (int kk = 0; kk < 4; kk++) {
                ull xp = pk2(xs4[kk], xs4[kk]);
                const ulonglong2* wq = (const ulonglong2*)(WT + (k4 * 4 + kk) * EMB);
                #pragma unroll
                for (int p = 0; p < 16; p++) {
                    ulonglong2 w2 = wq[p];
                    acc2[2 * p]     = fma2(xp, w2.x, acc2[2 * p]);
                    acc2[2 * p + 1] = fma2(xp, w2.y, acc2[2 * p + 1]);
                }
            }
        }
        #pragma unroll
        for (int p = 0; p < 32; p++) {
            float2 f = up2(acc2[p]);
            acc[2 * p] = f.x;
            acc[2 * p + 1] = f.y;
        }
        float4* Yr = (float4*)(Y + (size_t)row * EMB);
        #pragma unroll
        for (int q = 0; q < EMB / 4; q++)
            Yr[q] = make_float4(acc[4 * q], acc[4 * q + 1], acc[4 * q + 2], acc[4 * q + 3]);
    } else {
        #pragma unroll
        for (int j = 0; j < EMB; j++) acc[j] = 0.f;
    }
    #pragma unroll
    for (int j = 0; j < EMB; j++) {
        float v = acc[j];
        float v2 = v * v;
        #pragma unroll
        for (int o = 16; o; o >>= 1) {
            v  += __shfl_xor_sync(0xffffffffu, v, o);
            v2 += __shfl_xor_sync(0xffffffffu, v2, o);
        }
        if (lane == 0) { atomicAdd(&cs[j], v); atomicAdd(&cq[j], v2); }
    }
    __syncthreads();
    if (threadIdx.x < EMB) {
        atomicAdd(&g_sum2[threadIdx.x], cs[threadIdx.x]);
        atomicAdd(&g_sumsq2[threadIdx.x], cq[threadIdx.x]);
    }
}

// ---------------- final v2: proj-style tiled bn2+concat MLP ------------------
// 64-row tile per block; 8x4 micro-tile per thread; W staged transposed in
// shared; X staged per 64-col phase. ~20x less smem traffic than row/thread.
#define GEMM_TILE_ACC()                                                          \
    _Pragma("unroll 2")                                                          \
    for (int k4 = 0; k4 < 16; k4++) {                                            \
        ulonglong2 w2[4];                                                        \
        _Pragma("unroll")                                                        \
        for (int kk = 0; kk < 4; kk++)                                           \
            w2[kk] = *(const ulonglong2*)(WT + (k4 * 4 + kk) * PROJ_PAD + c16 * 4); \
        _Pragma("unroll")                                                        \
        for (int rr = 0; rr < 8; rr++) {                                         \
            float4 xf = *(const float4*)(XS + (rg * 8 + rr) * PROJ_PAD + k4 * 4);\
            ull xp;                                                              \
            xp = pk2(xf.x, xf.x); acc0[rr] = fma2(xp, w2[0].x, acc0[rr]); acc1[rr] = fma2(xp, w2[0].y, acc1[rr]); \
            xp = pk2(xf.y, xf.y); acc0[rr] = fma2(xp, w2[1].x, acc0[rr]); acc1[rr] = fma2(xp, w2[1].y, acc1[rr]); \
            xp = pk2(xf.z, xf.z); acc0[rr] = fma2(xp, w2[2].x, acc0[rr]); acc1[rr] = fma2(xp, w2[2].y, acc1[rr]); \
            xp = pk2(xf.w, xf.w); acc0[rr] = fma2(xp, w2[3].x, acc0[rr]); acc1[rr] = fma2(xp, w2[3].y, acc1[rr]); \
        }                                                                        \
    }

__global__ __launch_bounds__(128) void final_kernel(
    const float* __restrict__ right,
    const float* __restrict__ W1, const float* __restrict__ b1,
    const float* __restrict__ W2, const float* __restrict__ b2,
    float* __restrict__ out, int nR)
{
    __shared__ float WT[64 * PROJ_PAD];
    __shared__ float XS[64 * PROJ_PAD];
    __shared__ float sb[EMB], ssc[EMB], ssh[EMB];
    int tid = threadIdx.x;
    int rowBase = blockIdx.x * 64;
    int c16 = tid & 15;
    int rg  = tid >> 4;

    if (tid < EMB) {
        sb[tid]  = b1[tid];
        ssc[tid] = g_scale2[tid];
        ssh[tid] = g_shift2[tid];
    }
    // WT phase 1a: k in [0,64): WT[k][j] = W1[j*128 + k]
    for (int i = tid; i < EMB * EMB; i += 128) {
        int j = i >> 6, k = i & 63;
        WT[k * PROJ_PAD + j] = W1[j * 128 + k];
    }
    __syncthreads();
    // XS = bn2(conv tile)
    {
        const float4* C4 = (const float4*)g_conv;
        #pragma unroll
        for (int it = 0; it < 8; it++) {
            int idx = it * 128 + tid;
            int r = idx >> 4, k4 = idx & 15;
            int row = rowBase + r;
            float4 v = (row < nR) ? C4[(size_t)row * 16 + k4]
                                  : make_float4(0.f, 0.f, 0.f, 0.f);
            float4 scv = ((const float4*)ssc)[k4];
            float4 shv = ((const float4*)ssh)[k4];
            v.x = fmaf(v.x, scv.x, shv.x);
            v.y = fmaf(v.y, scv.y, shv.y);
            v.z = fmaf(v.z, scv.z, shv.z);
            v.w = fmaf(v.w, scv.w, shv.w);
            *(float4*)(XS + r * PROJ_PAD + k4 * 4) = v;
        }
    }
    __syncthreads();

    float4 b4 = ((const float4*)sb)[c16];
    ull acc0[8], acc1[8];
    #pragma unroll
    for (int rr = 0; rr < 8; rr++) { acc0[rr] = pk2(b4.x, b4.y); acc1[rr] = pk2(b4.z, b4.w); }
    GEMM_TILE_ACC();                      // phase 1a: conv half
    __syncthreads();

    // phase 1b: WT[k][j] = W1[j*128 + 64 + k]; XS = right tile
    for (int i = tid; i < EMB * EMB; i += 128) {
        int j = i >> 6, k = i & 63;
        WT[k * PROJ_PAD + j] = W1[j * 128 + 64 + k];
    }
    {
        const float4* R4 = (const float4*)right;
        #pragma unroll
        for (int it = 0; it < 8; it++) {
            int idx = it * 128 + tid;
            int r = idx >> 4, k4 = idx & 15;
            int row = rowBase + r;
            float4 v = (row < nR) ? R4[(size_t)row * 16 + k4]
                                  : make_float4(0.f, 0.f, 0.f, 0.f);
            *(float4*)(XS + r * PROJ_PAD + k4 * 4) = v;
        }
    }
    __syncthreads();
    GEMM_TILE_ACC();                      // phase 1b: right half
    __syncthreads();                      // done reading XS

    // relu(H) -> XS; stage W2^T and b2
    #pragma unroll
    for (int rr = 0; rr < 8; rr++) {
        float2 a = up2(acc0[rr]), b = up2(acc1[rr]);
        float* xp = XS + (rg * 8 + rr) * PROJ_PAD + c16 * 4;
        xp[0] = fmaxf(a.x, 0.f);
        xp[1] = fmaxf(a.y, 0.f);
        xp[2] = fmaxf(b.x, 0.f);
        xp[3] = fmaxf(b.y, 0.f);
    }
    if (tid < EMB) sb[tid] = b2[tid];
    for (int i = tid; i < EMB * EMB; i += 128) {
        int j = i >> 6, k = i & 63;
        WT[k * PROJ_PAD + j] = W2[j * 64 + k];
    }
    __syncthreads();

    b4 = ((const float4*)sb)[c16];
    #pragma unroll
    for (int rr = 0; rr < 8; rr++) { acc0[rr] = pk2(b4.x, b4.y); acc1[rr] = pk2(b4.z, b4.w); }
    GEMM_TILE_ACC();                      // phase 2

    float4* O4 = (float4*)out;
    #pragma unroll
    for (int rr = 0; rr < 8; rr++) {
        int row = rowBase + rg * 8 + rr;
        if (row < nR) {
            float2 a = up2(acc0[rr]), b = up2(acc1[rr]);
            O4[(size_t)row * 16 + c16] =
                make_float4(fmaxf(a.x, 0.f), fmaxf(a.y, 0.f),
                            fmaxf(b.x, 0.f), fmaxf(b.y, 0.f));
        }
    }
}

// ---------------- launch -----------------------------------------------------
extern "C" void kernel_launch(void* const* d_in, const int* in_sizes, int n_in,
                              void* d_out, int out_size)
{
    const float* left  = (const float*)d_in[0];
    const int*   eidx  = (const int*)d_in[1];
    const float* ef    = (const float*)d_in[2];
    const float* right = (const float*)d_in[3];
    int off = (n_in >= 19) ? 1 : 0;
    const float* W_left    = (const float*)d_in[4 + off];
    const float* b_left    = (const float*)d_in[5 + off];
    const float* W_edge    = (const float*)d_in[6 + off];
    const float* W_right   = (const float*)d_in[7 + off];
    const float* bn1_gamma = (const float*)d_in[8 + off];
    const float* bn1_beta  = (const float*)d_in[9 + off];
    const float* W_final   = (const float*)d_in[10 + off];
    const float* b_final   = (const float*)d_in[11 + off];
    const float* bn2_gamma = (const float*)d_in[12 + off];
    const float* bn2_beta  = (const float*)d_in[13 + off];
    const float* W_out1    = (const float*)d_in[14 + off];
    const float* b_out1    = (const float*)d_in[15 + off];
    const float* W_out2    = (const float*)d_in[16 + off];
    const float* b_out2    = (const float*)d_in[17 + off];
    float* out = (float*)d_out;

    int nL = in_sizes[0] / EMB;
    int nE = in_sizes[2];
    int nR = in_sizes[3] / EMB;

    float* Sp; cudaGetSymbolAddress((void**)&Sp, g_S);
    float* cp; cudaGetSymbolAddress((void**)&cp, g_conv);
    float* s1; cudaGetSymbolAddress((void**)&s1, g_sum1);
    float* q1; cudaGetSymbolAddress((void**)&q1, g_sumsq1);
    float* sc1; cudaGetSymbolAddress((void**)&sc1, g_scale1);
    float* sh1; cudaGetSymbolAddress((void**)&sh1, g_shift1);
    float* s2; cudaGetSymbolAddress((void**)&s2, g_sum2);
    float* q2; cudaGetSymbolAddress((void**)&q2, g_sumsq2);
    float* sc2; cudaGetSymbolAddress((void**)&sc2, g_scale2);
    float* sh2; cudaGetSymbolAddress((void**)&sh2, g_shift2);

    int nbL = (nL + 63) / 64;
    int nbR = (nR + 63) / 64;
    int nbRrow = (nR + 127) / 128;

    // idx 0) zero counters/stats
    zero_kernel<<<(nR + 255) / 256, 256>>>(nR);
    // idx 1) degree histogram
    count_kernel<<<1184, 256>>>(eidx + nE, nE);
    // idx 2) contiguous segment offsets
    assign_kernel<<<(nR + 255) / 256, 256>>>(nR);
    // idx 3) tiled projections (f32x2)             <- profiled launch (control)
    proj_kernel<<<nbL + nbR, 128>>>(left, W_left, b_left, right, W_right, nL, nR, nbL);
    // idx 4) bin {left_idx, f} into segments
    bin_kernel<<<1184, 256>>>(eidx, eidx + nE, ef, nE);
    // idx 5) BN1 stats (chunked, original order)
    stats_kernel<<<1184, 256>>>(eidx, eidx + nE, ef, W_edge, nE);
    // idx 6) BN1 finalize
    bn_fin_kernel<<<1, EMB>>>(s1, q1, bn1_gamma, bn1_beta, sc1, sh1, 1.0f / (float)nE);
    // idx 7) segment sum v5: per-node, batched gathers, no atomics
    seg_kernel<<<1184, 256>>>(W_edge, nR);
    // idx 8) conv GEMM (f32x2) + fused BN2 stats
    conv_stats_kernel<<<nbRrow, 128>>>(Sp, W_final, b_final, cp, nR);
    // idx 9) BN2 finalize
    bn_fin_kernel<<<1, EMB>>>(s2, q2, bn2_gamma, bn2_beta, sc2, sh2, 1.0f / (float)nR);
    // idx 10) final v2: tiled bn2+concat MLP
    final_kernel<<<nbR, 128>>>(right, W_out1, b_out1, W_out2, b_out2, out, nR);
}

// round 13
// speedup vs baseline: 1.8439x; 1.2697x over previous
#include <cuda_runtime.h>
#include <cuda_bf16.h>

#define EMB 64
#define BN_EPS 1e-5f
#define MAX_L 50000
#define MAX_R 100000
#define MAX_E 1100000

typedef unsigned long long ull;

// ---------------- f32x2 packed-FMA helpers (FFMA2) ---------------------------
__device__ __forceinline__ ull pk2(float lo, float hi) {
    ull r; asm("mov.b64 %0, {%1, %2};" : "=l"(r) : "f"(lo), "f"(hi)); return r;
}
__device__ __forceinline__ float2 up2(ull v) {
    float2 f; asm("mov.b64 {%0, %1}, %2;" : "=f"(f.x), "=f"(f.y) : "l"(v)); return f;
}
__device__ __forceinline__ ull fma2(ull a, ull b, ull c) {
    ull d; asm("fma.rn.f32x2 %0, %1, %2, %3;" : "=l"(d) : "l"(a), "l"(b), "l"(c)); return d;
}

// ---------------- scratch (static device globals; no allocation) -------------
__device__ float g_left_proj[MAX_L * EMB];
__device__ float g_right_proj[MAX_R * EMB];
__device__ float g_S[MAX_R * EMB];
__device__ float g_conv[MAX_R * EMB];
__device__ int   g_cnt[MAX_R];
__device__ int   g_off[MAX_R];
__device__ int   g_cur[MAX_R];
__device__ int   g_total;
__device__ int2  g_sorted[MAX_E];
__device__ float g_sum1[EMB], g_sumsq1[EMB];
__device__ float g_sum2[EMB], g_sumsq2[EMB];

// ---------------- zero scratch ----------------------------------------------
__global__ void zero_kernel(int nR) {
    int i = blockIdx.x * blockDim.x + threadIdx.x;
    int stride = gridDim.x * blockDim.x;
    for (int k = i; k < nR; k += stride) g_cnt[k] = 0;
    if (i < EMB) { g_sum1[i] = 0.f; g_sumsq1[i] = 0.f; g_sum2[i] = 0.f; g_sumsq2[i] = 0.f; }
    if (i == 0) g_total = 0;
}

// ---------------- count: histogram of right indices --------------------------
__global__ __launch_bounds__(256) void count_kernel(const int* __restrict__ idxR, int nE) {
    int i = blockIdx.x * blockDim.x + threadIdx.x;
    int stride = gridDim.x * blockDim.x;
    for (int e = i; e < nE; e += stride) atomicAdd(&g_cnt[idxR[e]], 1);
}

// ---------------- assign: contiguous segment offsets (order-free) ------------
__global__ __launch_bounds__(256) void assign_kernel(int nR) {
    int gtid = blockIdx.x * blockDim.x + threadIdx.x;
    int lane = threadIdx.x & 31;
    int stride = gridDim.x * blockDim.x;
    int niter = (nR + stride - 1) / stride;
    for (int it = 0; it < niter; it++) {
        int i = it * stride + gtid;
        int c = (i < nR) ? g_cnt[i] : 0;
        int s = c;
        #pragma unroll
        for (int d = 1; d < 32; d <<= 1) {
            int t = __shfl_up_sync(0xffffffffu, s, d);
            if (lane >= d) s += t;
        }
        int warpTotal = __shfl_sync(0xffffffffu, s, 31);
        int base = 0;
        if (lane == 31) base = atomicAdd(&g_total, warpTotal);
        base = __shfl_sync(0xffffffffu, base, 31);
        int off = base + s - c;
        if (i < nR) { g_off[i] = off; g_cur[i] = off; }
    }
}

// ---------------- bin: place {li, f} into per-node segments ------------------
__global__ __launch_bounds__(256) void bin_kernel(
    const int* __restrict__ idxL, const int* __restrict__ idxR,
    const float* __restrict__ ef, int nE)
{
    int i = blockIdx.x * blockDim.x + threadIdx.x;
    int stride = gridDim.x * blockDim.x;
    for (int e = i; e < nE; e += stride) {
        int r = idxR[e];
        int li = idxL[e];
        float f = ef[e];
        int pos = atomicAdd(&g_cur[r], 1);
        g_sorted[pos] = make_int2(li, __float_as_int(f));
    }
}

// ---------------- tiled projections (f32x2): 64x64 tile, 8x4 per thread ------
#define PROJ_PAD 68
__global__ __launch_bounds__(128) void proj_kernel(
    const float* __restrict__ XL, const float* __restrict__ WL, const float* __restrict__ bL,
    const float* __restrict__ XR, const float* __restrict__ WR,
    int nL, int nR, int nbL)
{
    bool isL = (int)blockIdx.x < nbL;
    const float* X = isL ? XL : XR;
    const float* W = isL ? WL : WR;
    float* Y = isL ? g_left_proj : g_right_proj;
    int n = isL ? nL : nR;
    int bid = isL ? blockIdx.x : blockIdx.x - nbL;
    int rowBase = bid * 64;

    __shared__ float WT[64 * PROJ_PAD];   // WT[k][j] = W[j][k]
    __shared__ float XS[64 * PROJ_PAD];
    __shared__ float bsh[EMB];
    for (int i = threadIdx.x; i < EMB * EMB; i += blockDim.x) {
        int j = i >> 6, k = i & 63;
        WT[k * PROJ_PAD + j] = W[i];
    }
    if (threadIdx.x < EMB) bsh[threadIdx.x] = isL ? bL[threadIdx.x] : 0.f;
    {
        const float4* X4 = (const float4*)X;
        #pragma unroll
        for (int it = 0; it < 8; it++) {
            int idx = it * 128 + threadIdx.x;
            int r = idx >> 4, k4 = idx & 15;
            int row = rowBase + r;
            float4 v = (row < n) ? X4[(size_t)row * 16 + k4]
                                 : make_float4(0.f, 0.f, 0.f, 0.f);
            *(float4*)(XS + r * PROJ_PAD + k4 * 4) = v;
        }
    }
    __syncthreads();

    int c16 = threadIdx.x & 15;
    int rg  = threadIdx.x >> 4;
    float4 b4 = ((const float4*)bsh)[c16];
    ull acc0[8], acc1[8];
    #pragma unroll
    for (int rr = 0; rr < 8; rr++) { acc0[rr] = pk2(b4.x, b4.y); acc1[rr] = pk2(b4.z, b4.w); }

    #pragma unroll 2
    for (int k4 = 0; k4 < 16; k4++) {
        ulonglong2 w2[4];
        #pragma unroll
        for (int kk = 0; kk < 4; kk++)
            w2[kk] = *(const ulonglong2*)(WT + (k4 * 4 + kk) * PROJ_PAD + c16 * 4);
        #pragma unroll
        for (int rr = 0; rr < 8; rr++) {
            float4 xf = *(const float4*)(XS + (rg * 8 + rr) * PROJ_PAD + k4 * 4);
            ull xp;
            xp = pk2(xf.x, xf.x); acc0[rr] = fma2(xp, w2[0].x, acc0[rr]); acc1[rr] = fma2(xp, w2[0].y, acc1[rr]);
            xp = pk2(xf.y, xf.y); acc0[rr] = fma2(xp, w2[1].x, acc0[rr]); acc1[rr] = fma2(xp, w2[1].y, acc1[rr]);
            xp = pk2(xf.z, xf.z); acc0[rr] = fma2(xp, w2[2].x, acc0[rr]); acc1[rr] = fma2(xp, w2[2].y, acc1[rr]);
            xp = pk2(xf.w, xf.w); acc0[rr] = fma2(xp, w2[3].x, acc0[rr]); acc1[rr] = fma2(xp, w2[3].y, acc1[rr]);
        }
    }

    float4* Y4 = (float4*)Y;
    #pragma unroll
    for (int rr = 0; rr < 8; rr++) {
        int row = rowBase + rg * 8 + rr;
        if (row < n) {
            float2 a = up2(acc0[rr]), b = up2(acc1[rr]);
            Y4[(size_t)row * 16 + c16] = make_float4(a.x, a.y, b.x, b.y);
        }
    }
}

// ---------------- stats v2: per-node over sorted array (seg-v5 shape) --------
__global__ __launch_bounds__(256) void stats_kernel(const float* __restrict__ Wedge, int nR)
{
    int lane = threadIdx.x & 31;
    int hl = lane & 15;
    unsigned hmask = (lane & 16) ? 0xFFFF0000u : 0x0000FFFFu;
    int grp = (blockIdx.x * blockDim.x + threadIdx.x) >> 4;
    int ngrp = (gridDim.x * blockDim.x) >> 4;
    float4 we = ((const float4*)Wedge)[hl];
    float4 s = make_float4(0.f, 0.f, 0.f, 0.f);
    float4 sq = make_float4(0.f, 0.f, 0.f, 0.f);
    const float4* LP = (const float4*)g_left_proj;
    const float4* RP = (const float4*)g_right_proj;

    for (int r = grp; r < nR; r += ngrp) {
        int cnt = g_cnt[r];
        int off = g_off[r];
        float4 rp = RP[(size_t)r * 16 + hl];
        for (int k = 0; k < cnt; k += 8) {
            int rem = cnt - k;
            int2 d = make_int2(0, 0);
            if (hl < 8 && hl < rem) d = g_sorted[off + k + hl];
            #pragma unroll
            for (int j = 0; j < 8; j++) {
                int lj = __shfl_sync(hmask, d.x, j, 16);
                int fb = __shfl_sync(hmask, d.y, j, 16);
                float4 lp = LP[(size_t)lj * 16 + hl];   // unconditional gather
                float fj = __int_as_float(fb);
                float m = (j < rem) ? 1.f : 0.f;
                float x, xm;
                x = fmaf(fj, we.x, lp.x + rp.x); xm = x * m; s.x += xm; sq.x = fmaf(xm, x, sq.x);
                x = fmaf(fj, we.y, lp.y + rp.y); xm = x * m; s.y += xm; sq.y = fmaf(xm, x, sq.y);
                x = fmaf(fj, we.z, lp.z + rp.z); xm = x * m; s.z += xm; sq.z = fmaf(xm, x, sq.z);
                x = fmaf(fj, we.w, lp.w + rp.w); xm = x * m; s.w += xm; sq.w = fmaf(xm, x, sq.w);
            }
        }
    }
    // halves hold same columns -> combine, then block/global reduce
    s.x += __shfl_xor_sync(0xffffffffu, s.x, 16);
    s.y += __shfl_xor_sync(0xffffffffu, s.y, 16);
    s.z += __shfl_xor_sync(0xffffffffu, s.z, 16);
    s.w += __shfl_xor_sync(0xffffffffu, s.w, 16);
    sq.x += __shfl_xor_sync(0xffffffffu, sq.x, 16);
    sq.y += __shfl_xor_sync(0xffffffffu, sq.y, 16);
    sq.z += __shfl_xor_sync(0xffffffffu, sq.z, 16);
    sq.w += __shfl_xor_sync(0xffffffffu, sq.w, 16);

    __shared__ float cs[EMB], cq[EMB];
    if (threadIdx.x < EMB) { cs[threadIdx.x] = 0.f; cq[threadIdx.x] = 0.f; }
    __syncthreads();
    if (lane < 16) {
        atomicAdd(&cs[4 * hl + 0], s.x);
        atomicAdd(&cs[4 * hl + 1], s.y);
        atomicAdd(&cs[4 * hl + 2], s.z);
        atomicAdd(&cs[4 * hl + 3], s.w);
        atomicAdd(&cq[4 * hl + 0], sq.x);
        atomicAdd(&cq[4 * hl + 1], sq.y);
        atomicAdd(&cq[4 * hl + 2], sq.z);
        atomicAdd(&cq[4 * hl + 3], sq.w);
    }
    __syncthreads();
    if (threadIdx.x < EMB) {
        atomicAdd(&g_sum1[threadIdx.x], cs[threadIdx.x]);
        atomicAdd(&g_sumsq1[threadIdx.x], cq[threadIdx.x]);
    }
}

// ---------------- seg v5 + in-block BN1 finalize -----------------------------
__global__ __launch_bounds__(256) void seg_kernel(
    const float* __restrict__ Wedge, const float* __restrict__ gamma,
    const float* __restrict__ beta, float invNE, int nR)
{
    __shared__ float ssc[EMB], ssh[EMB];
    if (threadIdx.x < EMB) {
        int c = threadIdx.x;
        float m = g_sum1[c] * invNE;
        float v = g_sumsq1[c] * invNE - m * m;
        float scv = gamma[c] * rsqrtf(v + BN_EPS);
        ssc[c] = scv;
        ssh[c] = beta[c] - m * scv;
    }
    __syncthreads();

    int lane = threadIdx.x & 31;
    int hl = lane & 15;
    unsigned hmask = (lane & 16) ? 0xFFFF0000u : 0x0000FFFFu;
    int grp = (blockIdx.x * blockDim.x + threadIdx.x) >> 4;
    int ngrp = (gridDim.x * blockDim.x) >> 4;
    float4 we = ((const float4*)Wedge)[hl];
    float4 sc = ((const float4*)ssc)[hl];
    float4 sh = ((const float4*)ssh)[hl];
    const float4* LP = (const float4*)g_left_proj;
    const float4* RP = (const float4*)g_right_proj;
    float4* Sv = (float4*)g_S;

    for (int r = grp; r < nR; r += ngrp) {
        int cnt = g_cnt[r];
        int off = g_off[r];
        float4 rp = RP[(size_t)r * 16 + hl];
        float4 acc = make_float4(0.f, 0.f, 0.f, 0.f);
        for (int k = 0; k < cnt; k += 8) {
            int rem = cnt - k;
            int2 d = make_int2(0, 0);
            if (hl < 8 && hl < rem) d = g_sorted[off + k + hl];
            #pragma unroll
            for (int j = 0; j < 8; j++) {
                int lj = __shfl_sync(hmask, d.x, j, 16);
                int fb = __shfl_sync(hmask, d.y, j, 16);
                float4 lp = LP[(size_t)lj * 16 + hl];
                float fj = __int_as_float(fb);
                float m = (j < rem) ? 1.f : 0.f;
                float x, y;
                x = fmaf(fj, we.x, lp.x + rp.x); y = fmaxf(fmaf(x, sc.x, sh.x), 0.f); acc.x = fmaf(y, m, acc.x);
                x = fmaf(fj, we.y, lp.y + rp.y); y = fmaxf(fmaf(x, sc.y, sh.y), 0.f); acc.y = fmaf(y, m, acc.y);
                x = fmaf(fj, we.z, lp.z + rp.z); y = fmaxf(fmaf(x, sc.z, sh.z), 0.f); acc.z = fmaf(y, m, acc.z);
                x = fmaf(fj, we.w, lp.w + rp.w); y = fmaxf(fmaf(x, sc.w, sh.w), 0.f); acc.w = fmaf(y, m, acc.w);
            }
        }
        Sv[(size_t)r * 16 + hl] = acc;
    }
}

// ---------------- conv v2: tiled S @ Wf^T + cnt*b, fused BN2 stats -----------
__global__ __launch_bounds__(128) void conv_kernel(
    const float* __restrict__ W, const float* __restrict__ bias, int nR)
{
    __shared__ float WT[64 * PROJ_PAD];
    __shared__ float XS[64 * PROJ_PAD];
    __shared__ float bsh[EMB], scnt[EMB];
    __shared__ float cs[EMB], cq[EMB];
    int tid = threadIdx.x;
    int rowBase = blockIdx.x * 64;
    int c16 = tid & 15;
    int rg  = tid >> 4;

    for (int i = tid; i < EMB * EMB; i += 128) {
        int j = i >> 6, k = i & 63;
        WT[k * PROJ_PAD + j] = W[i];
    }
    if (tid < EMB) {
        bsh[tid] = bias[tid];
        int row = rowBase + tid;
        scnt[tid] = (row < nR) ? (float)g_cnt[row] : 0.f;
        cs[tid] = 0.f;
        cq[tid] = 0.f;
    }
    {
        const float4* X4 = (const float4*)g_S;
        #pragma unroll
        for (int it = 0; it < 8; it++) {
            int idx = it * 128 + tid;
            int r = idx >> 4, k4 = idx & 15;
            int row = rowBase + r;
            float4 v = (row < nR) ? X4[(size_t)row * 16 + k4]
                                  : make_float4(0.f, 0.f, 0.f, 0.f);
            *(float4*)(XS + r * PROJ_PAD + k4 * 4) = v;
        }
    }
    __syncthreads();

    float4 b4 = ((const float4*)bsh)[c16];
    ull acc0[8], acc1[8];
    #pragma unroll
    for (int rr = 0; rr < 8; rr++) {
        float c = scnt[rg * 8 + rr];
        acc0[rr] = pk2(b4.x * c, b4.y * c);
        acc1[rr] = pk2(b4.z * c, b4.w * c);
    }

    #pragma unroll 2
    for (int k4 = 0; k4 < 16; k4++) {
        ulonglong2 w2[4];
        #pragma unroll
        for (int kk = 0; kk < 4; kk++)
            w2[kk] = *(const ulonglong2*)(WT + (k4 * 4 + kk) * PROJ_PAD + c16 * 4);
        #pragma unroll
        for (int rr = 0; rr < 8; rr++) {
            float4 xf = *(const float4*)(XS + (rg * 8 + rr) * PROJ_PAD + k4 * 4);
            ull xp;
            xp = pk2(xf.x, xf.x); acc0[rr] = fma2(xp, w2[0].x, acc0[rr]); acc1[rr] = fma2(xp, w2[0].y, acc1[rr]);
            xp = pk2(xf.y, xf.y); acc0[rr] = fma2(xp, w2[1].x, acc0[rr]); acc1[rr] = fma2(xp, w2[1].y, acc1[rr]);
            xp = pk2(xf.z, xf.z); acc0[rr] = fma2(xp, w2[2].x, acc0[rr]); acc1[rr] = fma2(xp, w2[2].y, acc1[rr]);
            xp = pk2(xf.w, xf.w); acc0[rr] = fma2(xp, w2[3].x, acc0[rr]); acc1[rr] = fma2(xp, w2[3].y, acc1[rr]);
        }
    }

    // write Y and accumulate BN2 column stats (OOB rows produce zeros)
    float4 ps = make_float4(0.f, 0.f, 0.f, 0.f);
    float4 pq = make_float4(0.f, 0.f, 0.f, 0.f);
    float4* Y4 = (float4*)g_conv;
    #pragma unroll
    for (int rr = 0; rr < 8; rr++) {
        int row = rowBase + rg * 8 + rr;
        float2 a = up2(acc0[rr]), b = up2(acc1[rr]);
        if (row < nR) {
            Y4[(size_t)row * 16 + c16] = make_float4(a.x, a.y, b.x, b.y);
            ps.x += a.x; pq.x = fmaf(a.x, a.x, pq.x);
            ps.y += a.y; pq.y = fmaf(a.y, a.y, pq.y);
            ps.z += b.x; pq.z = fmaf(b.x, b.x, pq.z);
            ps.w += b.y; pq.w = fmaf(b.y, b.y, pq.w);
        }
    }
    atomicAdd(&cs[4 * c16 + 0], ps.x);
    atomicAdd(&cs[4 * c16 + 1], ps.y);
    atomicAdd(&cs[4 * c16 + 2], ps.z);
    atomicAdd(&cs[4 * c16 + 3], ps.w);
    atomicAdd(&cq[4 * c16 + 0], pq.x);
    atomicAdd(&cq[4 * c16 + 1], pq.y);
    atomicAdd(&cq[4 * c16 + 2], pq.z);
    atomicAdd(&cq[4 * c16 + 3], pq.w);
    __syncthreads();
    if (tid < EMB) {
        atomicAdd(&g_sum2[tid], cs[tid]);
        atomicAdd(&g_sumsq2[tid], cq[tid]);
    }
}

// ---------------- final v2 + in-block BN2 finalize ---------------------------
#define GEMM_TILE_ACC()                                                          \
    _Pragma("unroll 2")                                                          \
    for (int k4 = 0; k4 < 16; k4++) {                                            \
        ulonglong2 w2[4];                                                        \
        _Pragma("unroll")                                                        \
        for (int kk = 0; kk < 4; kk++)                                           \
            w2[kk] = *(const ulonglong2*)(WT + (k4 * 4 + kk) * PROJ_PAD + c16 * 4); \
        _Pragma("unroll")                                                        \
        for (int rr = 0; rr < 8; rr++) {                                         \
            float4 xf = *(const float4*)(XS + (rg * 8 + rr) * PROJ_PAD + k4 * 4);\
            ull xp;                                                              \
            xp = pk2(xf.x, xf.x); acc0[rr] = fma2(xp, w2[0].x, acc0[rr]); acc1[rr] = fma2(xp, w2[0].y, acc1[rr]); \
            xp = pk2(xf.y, xf.y); acc0[rr] = fma2(xp, w2[1].x, acc0[rr]); acc1[rr] = fma2(xp, w2[1].y, acc1[rr]); \
            xp = pk2(xf.z, xf.z); acc0[rr] = fma2(xp, w2[2].x, acc0[rr]); acc1[rr] = fma2(xp, w2[2].y, acc1[rr]); \
            xp = pk2(xf.w, xf.w); acc0[rr] = fma2(xp, w2[3].x, acc0[rr]); acc1[rr] = fma2(xp, w2[3].y, acc1[rr]); \
        }                                                                        \
    }

__global__ __launch_bounds__(128) void final_kernel(
    const float* __restrict__ right,
    const float* __restrict__ W1, const float* __restrict__ b1,
    const float* __restrict__ W2, const float* __restrict__ b2,
    const float* __restrict__ gamma, const float* __restrict__ beta,
    float invNR, float* __restrict__ out, int nR)
{
    __shared__ float WT[64 * PROJ_PAD];
    __shared__ float XS[64 * PROJ_PAD];
    __shared__ float sb[EMB], ssc[EMB], ssh[EMB];
    int tid = threadIdx.x;
    int rowBase = blockIdx.x * 64;
    int c16 = tid & 15;
    int rg  = tid >> 4;

    if (tid < EMB) {
        sb[tid] = b1[tid];
        float m = g_sum2[tid] * invNR;
        float v = g_sumsq2[tid] * invNR - m * m;
        float scv = gamma[tid] * rsqrtf(v + BN_EPS);
        ssc[tid] = scv;
        ssh[tid] = beta[tid] - m * scv;
    }
    // WT phase 1a: k in [0,64): WT[k][j] = W1[j*128 + k]
    for (int i = tid; i < EMB * EMB; i += 128) {
        int j = i >> 6, k = i & 63;
        WT[k * PROJ_PAD + j] = W1[j * 128 + k];
    }
    __syncthreads();
    // XS = bn2(conv tile)
    {
        const float4* C4 = (const float4*)g_conv;
        #pragma unroll
        for (int it = 0; it < 8; it++) {
            int idx = it * 128 + tid;
            int r = idx >> 4, k4 = idx & 15;
            int row = rowBase + r;
            float4 v = (row < nR) ? C4[(size_t)row * 16 + k4]
                                  : make_float4(0.f, 0.f, 0.f, 0.f);
            float4 scv = ((const float4*)ssc)[k4];
            float4 shv = ((const float4*)ssh)[k4];
            v.x = fmaf(v.x, scv.x, shv.x);
            v.y = fmaf(v.y, scv.y, shv.y);
            v.z = fmaf(v.z, scv.z, shv.z);
            v.w = fmaf(v.w, scv.w, shv.w);
            *(float4*)(XS + r * PROJ_PAD + k4 * 4) = v;
        }
    }
    __syncthreads();

    float4 b4 = ((const float4*)sb)[c16];
    ull acc0[8], acc1[8];
    #pragma unroll
    for (int rr = 0; rr < 8; rr++) { acc0[rr] = pk2(b4.x, b4.y); acc1[rr] = pk2(b4.z, b4.w); }
    GEMM_TILE_ACC();                      // phase 1a: conv half
    __syncthreads();

    // phase 1b: WT[k][j] = W1[j*128 + 64 + k]; XS = right tile
    for (int i = tid; i < EMB * EMB; i += 128) {
        int j = i >> 6, k = i & 63;
        WT[k * PROJ_PAD + j] = W1[j * 128 + 64 + k];
    }
    {
        const float4* R4 = (const float4*)right;
        #pragma unroll
        for (int it = 0; it < 8; it++) {
            int idx = it * 128 + tid;
            int r = idx >> 4, k4 = idx & 15;
            int row = rowBase + r;
            float4 v = (row < nR) ? R4[(size_t)row * 16 + k4]
                                  : make_float4(0.f, 0.f, 0.f, 0.f);
            *(float4*)(XS + r * PROJ_PAD + k4 * 4) = v;
        }
    }
    __syncthreads();
    GEMM_TILE_ACC();                      // phase 1b: right half
    __syncthreads();

    // relu(H) -> XS; stage W2^T and b2
    #pragma unroll
    for (int rr = 0; rr < 8; rr++) {
        float2 a = up2(acc0[rr]), b = up2(acc1[rr]);
        float* xp = XS + (rg * 8 + rr) * PROJ_PAD + c16 * 4;
        xp[0] = fmaxf(a.x, 0.f);
        xp[1] = fmaxf(a.y, 0.f);
        xp[2] = fmaxf(b.x, 0.f);
        xp[3] = fmaxf(b.y, 0.f);
    }
    if (tid < EMB) sb[tid] = b2[tid];
    for (int i = tid; i < EMB * EMB; i += 128) {
        int j = i >> 6, k = i & 63;
        WT[k * PROJ_PAD + j] = W2[j * 64 + k];
    }
    __syncthreads();

    b4 = ((const float4*)sb)[c16];
    #pragma unroll
    for (int rr = 0; rr < 8; rr++) { acc0[rr] = pk2(b4.x, b4.y); acc1[rr] = pk2(b4.z, b4.w); }
    GEMM_TILE_ACC();                      // phase 2

    float4* O4 = (float4*)out;
    #pragma unroll
    for (int rr = 0; rr < 8; rr++) {
        int row = rowBase + rg * 8 + rr;
        if (row < nR) {
            float2 a = up2(acc0[rr]), b = up2(acc1[rr]);
            O4[(size_t)row * 16 + c16] =
                make_float4(fmaxf(a.x, 0.f), fmaxf(a.y, 0.f),
                            fmaxf(b.x, 0.f), fmaxf(b.y, 0.f));
        }
    }
}

// ---------------- launch -----------------------------------------------------
extern "C" void kernel_launch(void* const* d_in, const int* in_sizes, int n_in,
                              void* d_out, int out_size)
{
    const float* left  = (const float*)d_in[0];
    const int*   eidx  = (const int*)d_in[1];
    const float* ef    = (const float*)d_in[2];
    const float* right = (const float*)d_in[3];
    int off = (n_in >= 19) ? 1 : 0;
    const float* W_left    = (const float*)d_in[4 + off];
    const float* b_left    = (const float*)d_in[5 + off];
    const float* W_edge    = (const float*)d_in[6 + off];
    const float* W_right   = (const float*)d_in[7 + off];
    const float* bn1_gamma = (const float*)d_in[8 + off];
    const float* bn1_beta  = (const float*)d_in[9 + off];
    const float* W_final   = (const float*)d_in[10 + off];
    const float* b_final   = (const float*)d_in[11 + off];
    const float* bn2_gamma = (const float*)d_in[12 + off];
    const float* bn2_beta  = (const float*)d_in[13 + off];
    const float* W_out1    = (const float*)d_in[14 + off];
    const float* b_out1    = (const float*)d_in[15 + off];
    const float* W_out2    = (const float*)d_in[16 + off];
    const float* b_out2    = (const float*)d_in[17 + off];
    float* out = (float*)d_out;

    int nL = in_sizes[0] / EMB;
    int nE = in_sizes[2];
    int nR = in_sizes[3] / EMB;

    int nbL = (nL + 63) / 64;
    int nbR = (nR + 63) / 64;

    // idx 0) zero counters/stats
    zero_kernel<<<(nR + 255) / 256, 256>>>(nR);
    // idx 1) degree histogram
    count_kernel<<<1184, 256>>>(eidx + nE, nE);
    // idx 2) contiguous segment offsets
    assign_kernel<<<(nR + 255) / 256, 256>>>(nR);
    // idx 3) tiled projections (f32x2)             <- profiled launch (control)
    proj_kernel<<<nbL + nbR, 128>>>(left, W_left, b_left, right, W_right, nL, nR, nbL);
    // idx 4) bin {left_idx, f} into segments
    bin_kernel<<<1184, 256>>>(eidx, eidx + nE, ef, nE);
    // idx 5) BN1 stats v2: per-node over sorted array
    stats_kernel<<<1184, 256>>>(W_edge, nR);
    // idx 6) segment sum v5 (+ in-block bn1 finalize)
    seg_kernel<<<1184, 256>>>(W_edge, bn1_gamma, bn1_beta, 1.0f / (float)nE, nR);
    // idx 7) conv v2: tiled GEMM + fused BN2 stats
    conv_kernel<<<nbR, 128>>>(W_final, b_final, nR);
    // idx 8) final v2 (+ in-block bn2 finalize)
    final_kernel<<<nbR, 128>>>(right, W_out1, b_out1, W_out2, b_out2,
                               bn2_gamma, bn2_beta, 1.0f / (float)nR, out, nR);
}